// round 13
// baseline (speedup 1.0000x reference)
#include <cuda_runtime.h>
#include <cstdint>

constexpr int IDIM = 384;
constexpr int JDIM = 384;
constexpr int NPIX = IDIM * JDIM;      // 147456
constexpr int CH   = 128;
constexpr int NH   = 4;
constexpr int HD   = 32;
constexpr float LN_EPS = 1e-5f;
constexpr float QSCALE = 0.17677669529663687f;  // 1/sqrt(32)
constexpr float LOG2E  = 1.4426950408889634f;

// Static device scratch
__device__ float g_qkvg[(size_t)NPIX * 512];   // q|k|-|g (q,k tf32 slot16-interleaved, k rows perm8'd, q pre-scaled; g fp32)
__device__ float g_vt[(size_t)IDIM * NH * HD * JDIM];  // V^T: [i][h][d][permv(j)], tf32 bits
__device__ float g_tri[(size_t)NH * NPIX];     // tri bias * log2e, k-index permv'd
__device__ float g_mb[(size_t)NPIX];           // 1e9*log2e*(mask-1), k-index permv'd
__device__ float g_og[(size_t)NPIX * CH];      // gated attn out, natural, tf32 bits
__device__ uint32_t g_wt[5][128][128];         // transposed tf32 weights, k slot16'd; wq/wk N-cols slot16'd

// ---------------------------------------------------------------------------
__device__ __forceinline__ uint32_t f2tf(float f) {
    uint32_t u;
    asm("cvt.rna.tf32.f32 %0, %1;" : "=r"(u) : "f"(f));
    return u;
}
__device__ __forceinline__ float ex2(float x) {
    float y;
    asm("ex2.approx.f32 %0, %1;" : "=f"(y) : "f"(x));
    return y;
}
__device__ __forceinline__ void mma8(float* d, const uint32_t* a,
                                     uint32_t b0, uint32_t b1) {
    asm volatile(
        "mma.sync.aligned.m16n8k8.row.col.f32.tf32.tf32.f32 "
        "{%0,%1,%2,%3}, {%4,%5,%6,%7}, {%8,%9}, {%0,%1,%2,%3};\n"
        : "+f"(d[0]), "+f"(d[1]), "+f"(d[2]), "+f"(d[3])
        : "r"(a[0]), "r"(a[1]), "r"(a[2]), "r"(a[3]), "r"(b0), "r"(b1));
}
__device__ __forceinline__ void cpa16(void* dst, const void* src) {
    unsigned d = (unsigned)__cvta_generic_to_shared(dst);
    asm volatile("cp.async.cg.shared.global [%0], [%1], 16;\n"
                 :: "r"(d), "l"(src));
}
// pair-interleave within groups of 8 (== mma fragment slot map)
__device__ __forceinline__ int perm8(int x) {
    return (x & ~7) | (((x & 3) << 1) | ((x >> 2) & 1));
}
// dim d -> storage pos: chunk-PAIR fragment words contiguous (16B = 4 frag words)
__device__ __forceinline__ int slot16(int x) {
    int w = x & 15, c = w >> 3, v = w & 7;
    return (x & ~15) | ((v & 3) << 2) | (c << 1) | (v >> 2);
}
// key j -> storage col: sigma within 8, then chunk-pair interleave
__device__ __forceinline__ int permv(int j) {
    int p8 = perm8(j) & 7;
    int c  = (j >> 3) & 1;
    return (j & ~15) | ((p8 >> 1) << 2) | (c << 1) | (p8 & 1);
}

// ---------------------------------------------------------------------------
// Kernel A: one-shot weight prep. Transpose + tf32 + k slot16 (paired frag
// loads in proj). wq/wk N-cols get slot16 (attn Q/K pairing); wq absorbs scale.
// ---------------------------------------------------------------------------
__global__ void prepw_kernel(const float* __restrict__ wq,
                             const float* __restrict__ wk,
                             const float* __restrict__ wv,
                             const float* __restrict__ wg,
                             const float* __restrict__ wo) {
    const float* Ws[5] = { wq, wk, wv, wg, wo };
    int wi = blockIdx.x;
    int k  = threadIdx.x;
    float scale = (wi == 0) ? (QSCALE * LOG2E) : 1.0f;
    const float4* src = (const float4*)(Ws[wi] + (size_t)k * 128);
    int pk = slot16(k);
    bool nperm = (wi <= 1);
    #pragma unroll
    for (int c = 0; c < 32; ++c) {
        float4 v = src[c];
        float vv[4] = { v.x, v.y, v.z, v.w };
        #pragma unroll
        for (int e = 0; e < 4; ++e) {
            int n = c * 4 + e;
            int np = nperm ? slot16(n) : n;
            g_wt[wi][np][pk] = f2tf(vv[e] * scale);
        }
    }
}

// ---------------------------------------------------------------------------
// Kernel B: permv'd, log2e-scaled mask-bias rows
// ---------------------------------------------------------------------------
__global__ void maskb_kernel(const float* __restrict__ mask) {
    int idx = blockIdx.x * 256 + threadIdx.x;
    if (idx >= NPIX) return;
    int i = idx / JDIM;
    int j = idx - i * JDIM;
    g_mb[(size_t)i * JDIM + permv(j)] = (1e9f * LOG2E) * (mask[idx] - 1.0f);
}

// ---------------------------------------------------------------------------
// Kernel C: fused {LayerNorm + tri-proj} + tf32 mma projections.
// A and W staged in slot16 k-layout -> mainloop fragment loads are LDS.128
// (each feeding 4 MMAs). PPAD 144 (== 16 mod 32): conflict-free LDS.128.
// W staged via cp.async hidden under epilogue.
// ---------------------------------------------------------------------------
constexpr int PPAD = 144;
constexpr size_t SMEM_PROJ = (size_t)(256 * PPAD + 128 * PPAD + 768) * 4;

__global__ void __launch_bounds__(512) proj_kernel(
        int wbase, int nw, const float* __restrict__ bias,
        const float* __restrict__ X,
        const float* __restrict__ ln_w, const float* __restrict__ ln_b,
        const float* __restrict__ w_tri,
        float* __restrict__ Cext, int amode) {
    extern __shared__ uint32_t smu[];
    uint32_t* Asu = smu;                    // [256][PPAD]
    uint32_t* Wtu = smu + 256 * PPAD;       // [128][PPAD]
    float* lnw  = (float*)(Wtu + 128 * PPAD);
    float* lnb  = lnw + 128;
    float* wtri = lnb + 128;

    const int tid = threadIdx.x;
    const int bm  = blockIdx.x * 256;

    // prefetch W0 while A is being staged
    {
        int n = tid >> 2, q4 = tid & 3;
        const float4* src = (const float4*)&g_wt[wbase][n][q4 * 32];
        uint32_t* dst = Wtu + n * PPAD + q4 * 32;
        #pragma unroll
        for (int c = 0; c < 8; ++c)
            cpa16(dst + c * 4, src + c);
        asm volatile("cp.async.commit_group;\n");
    }

    if (amode == 0) {
        if (tid < 32)        ((float4*)lnw)[tid]       = ((const float4*)ln_w)[tid];
        else if (tid < 64)   ((float4*)lnb)[tid - 32]  = ((const float4*)ln_b)[tid - 32];
        else if (tid < 192)  ((float4*)wtri)[tid - 64] = ((const float4*)w_tri)[tid - 64];
    }
    __syncthreads();

    // ---- stage A (slot16 k-layout) ----
    {
        int r = tid >> 1, half = tid & 1;
        int gw = bm + r;
        uint32_t* arow = Asu + r * PPAD;

        if (amode == 0) {
            const float4* xr = (const float4*)(X + (size_t)gw * 128 + half * 64);
            float s = 0.f, ss = 0.f;
            #pragma unroll
            for (int c = 0; c < 16; ++c) {
                float4 v = xr[c];
                s  += v.x + v.y + v.z + v.w;
                ss += v.x * v.x + v.y * v.y + v.z * v.z + v.w * v.w;
            }
            s  += __shfl_xor_sync(0xffffffffu, s, 1);
            ss += __shfl_xor_sync(0xffffffffu, ss, 1);
            float mu = s * (1.0f / 128.0f);
            float rs = rsqrtf(fmaxf(ss * (1.0f / 128.0f) - mu * mu, 0.f) + LN_EPS);

            float th0 = 0.f, th1 = 0.f, th2 = 0.f, th3 = 0.f;
            #pragma unroll
            for (int c = 0; c < 16; ++c) {
                float4 v = xr[c];
                float vs[4] = { v.x, v.y, v.z, v.w };
                #pragma unroll
                for (int e = 0; e < 4; ++e) {
                    int ch = half * 64 + c * 4 + e;
                    float xn = (vs[e] - mu) * rs * lnw[ch] + lnb[ch];
                    float4 wt = ((const float4*)wtri)[ch];
                    th0 += xn * wt.x; th1 += xn * wt.y;
                    th2 += xn * wt.z; th3 += xn * wt.w;
                    arow[slot16(ch)] = f2tf(xn);
                }
            }
            th0 += __shfl_xor_sync(0xffffffffu, th0, 1);
            th1 += __shfl_xor_sync(0xffffffffu, th1, 1);
            th2 += __shfl_xor_sync(0xffffffffu, th2, 1);
            th3 += __shfl_xor_sync(0xffffffffu, th3, 1);
            if (half == 0) {
                size_t dst = (size_t)permv(gw);
                g_tri[0 * (size_t)NPIX + dst] = th0 * LOG2E;
                g_tri[1 * (size_t)NPIX + dst] = th1 * LOG2E;
                g_tri[2 * (size_t)NPIX + dst] = th2 * LOG2E;
                g_tri[3 * (size_t)NPIX + dst] = th3 * LOG2E;
            }
        } else {
            const float4* xr = (const float4*)(g_og + (size_t)gw * 128 + half * 64);
            #pragma unroll
            for (int c = 0; c < 16; ++c) {
                float4 v = xr[c];
                int ch = half * 64 + c * 4;
                arow[slot16(ch + 0)] = __float_as_uint(v.x);
                arow[slot16(ch + 1)] = __float_as_uint(v.y);
                arow[slot16(ch + 2)] = __float_as_uint(v.z);
                arow[slot16(ch + 3)] = __float_as_uint(v.w);
            }
        }
    }

    const int w = tid >> 5, lane = tid & 31;
    const int g = lane >> 2, t = lane & 3;
    const int wm = w >> 1, wn = w & 1;

    for (int wi = 0; wi < nw; ++wi) {
        asm volatile("cp.async.wait_group 0;\n");
        __syncthreads();

        float acc[2][8][4];
        #pragma unroll
        for (int mi = 0; mi < 2; ++mi)
            #pragma unroll
            for (int nt = 0; nt < 8; ++nt)
                #pragma unroll
                for (int j = 0; j < 4; ++j) acc[mi][nt][j] = 0.0f;

        // kk-pairs: one LDS.128 per operand feeds 2 chunks
        #pragma unroll
        for (int P = 0; P < 8; ++P) {
            uint32_t a[2][2][4];   // [mi][chunk]
            #pragma unroll
            for (int mi = 0; mi < 2; ++mi) {
                int rb = wm * 32 + mi * 16;
                uint4 u0 = *(const uint4*)&Asu[(rb + g) * PPAD + P * 16 + 4 * t];
                uint4 u1 = *(const uint4*)&Asu[(rb + g + 8) * PPAD + P * 16 + 4 * t];
                a[mi][0][0] = u0.x; a[mi][0][2] = u0.y;
                a[mi][1][0] = u0.z; a[mi][1][2] = u0.w;
                a[mi][0][1] = u1.x; a[mi][0][3] = u1.y;
                a[mi][1][1] = u1.z; a[mi][1][3] = u1.w;
            }
            #pragma unroll
            for (int nt = 0; nt < 8; ++nt) {
                uint4 bp = *(const uint4*)&Wtu[(wn * 64 + nt * 8 + g) * PPAD + P * 16 + 4 * t];
                mma8(acc[0][nt], a[0][0], bp.x, bp.y);
                mma8(acc[0][nt], a[0][1], bp.z, bp.w);
                mma8(acc[1][nt], a[1][0], bp.x, bp.y);
                mma8(acc[1][nt], a[1][1], bp.z, bp.w);
            }
        }

        __syncthreads();   // all warps done reading Wtu
        if (wi + 1 < nw) { // prefetch next W; copy hides under the epilogue
            int n = tid >> 2, q4 = tid & 3;
            const float4* src = (const float4*)&g_wt[wbase + wi + 1][n][q4 * 32];
            uint32_t* dst = Wtu + n * PPAD + q4 * 32;
            #pragma unroll
            for (int c = 0; c < 8; ++c)
                cpa16(dst + c * 4, src + c);
            asm volatile("cp.async.commit_group;\n");
        }

        // epilogue
        #pragma unroll
        for (int mi = 0; mi < 2; ++mi) {
            int row0 = bm + wm * 32 + mi * 16 + g;
            int row1 = row0 + 8;
            int i0 = row0 / JDIM, j0 = row0 - i0 * JDIM;
            int i1 = row1 / JDIM, j1 = row1 - i1 * JDIM;
            int pj0 = permv(j0), pj1 = permv(j1);
            #pragma unroll
            for (int nt = 0; nt < 8; ++nt) {
                int col = wn * 64 + nt * 8 + 2 * t;
                float v0 = acc[mi][nt][0], v1 = acc[mi][nt][1];
                float v2 = acc[mi][nt][2], v3 = acc[mi][nt][3];
                if (amode == 0) {
                    if (wi <= 1) {          // q/k: cols already slot16 order
                        int r0 = (wi == 1) ? perm8(row0) : row0;
                        int r1 = (wi == 1) ? perm8(row1) : row1;
                        float2 a0 = { __uint_as_float(f2tf(v0)), __uint_as_float(f2tf(v1)) };
                        float2 a1 = { __uint_as_float(f2tf(v2)), __uint_as_float(f2tf(v3)) };
                        *(float2*)(g_qkvg + (size_t)r0 * 512 + wi * 128 + col) = a0;
                        *(float2*)(g_qkvg + (size_t)r1 * 512 + wi * 128 + col) = a1;
                    } else if (wi == 2) {   // v: transposed tf32 into g_vt, permv cols
                        int hh = col >> 5, d0 = col & 31;
                        size_t b0 = ((size_t)(i0 * NH + hh) * HD + d0) * JDIM;
                        size_t b1 = ((size_t)(i1 * NH + hh) * HD + d0) * JDIM;
                        g_vt[b0 + pj0]        = __uint_as_float(f2tf(v0));
                        g_vt[b0 + JDIM + pj0] = __uint_as_float(f2tf(v1));
                        g_vt[b1 + pj1]        = __uint_as_float(f2tf(v2));
                        g_vt[b1 + JDIM + pj1] = __uint_as_float(f2tf(v3));
                    } else {                // g: + bias, fp32 natural
                        float2 bb = *(const float2*)(bias + col);
                        float2 a0 = { v0 + bb.x, v1 + bb.y };
                        float2 a1 = { v2 + bb.x, v3 + bb.y };
                        *(float2*)(g_qkvg + (size_t)row0 * 512 + 384 + col) = a0;
                        *(float2*)(g_qkvg + (size_t)row1 * 512 + 384 + col) = a1;
                    }
                } else {
                    float2 bb = *(const float2*)(bias + col);
                    float2 a0 = { v0 + bb.x, v1 + bb.y };
                    float2 a1 = { v2 + bb.x, v3 + bb.y };
                    *(float2*)(Cext + (size_t)row0 * 128 + col) = a0;
                    *(float2*)(Cext + (size_t)row1 * 128 + col) = a1;
                }
            }
        }
    }
}

// ---------------------------------------------------------------------------
// Kernel D: tf32 mma flash attention. ONE block per (h, i): 384 threads,
// 12 warps x 32 q-rows (full q row) -> K/V staged ONCE per (h,i) instead of
// twice. All fragment loads 128-bit. Row stride 80 (== 16 mod 32).
// ---------------------------------------------------------------------------
constexpr int KS_W = 80;
constexpr int VT_W = 80;
constexpr size_t SMEM_ATTN = (size_t)(2 * 64 * KS_W + 2 * 32 * VT_W + 384) * 4;

__global__ void __launch_bounds__(384, 1) attn_mma() {
    extern __shared__ uint32_t sm[];
    uint32_t* Ks = sm;                    // [2][64][KS_W]
    uint32_t* Vt = sm + 2 * 64 * KS_W;    // [2][32][VT_W]
    float*    mb = (float*)(Vt + 2 * 32 * VT_W);

    const int h   = blockIdx.x;       // 0..3
    const int i   = blockIdx.y;       // 0..383
    const int tid = threadIdx.x;
    const int w = tid >> 5, lane = tid & 31;
    const int g = lane >> 2, t = lane & 3;

    const float* kbase = g_qkvg + ((size_t)i * JDIM) * 512 + 128 + h * HD;
    const float* vbase = g_vt + (size_t)(i * NH + h) * HD * JDIM;

    auto stage = [&](int st, int k0) {
        #pragma unroll
        for (int c = tid; c < 1024; c += 384) {
            if (c < 512) {
                int r = c >> 3, seg = c & 7;
                cpa16(Ks + (st * 64 + r) * KS_W + seg * 4,
                      kbase + (size_t)(k0 + r) * 512 + seg * 4);
            } else {
                int vc = c - 512;
                int d = vc >> 4, seg = vc & 15;
                cpa16(Vt + (st * 32 + d) * VT_W + seg * 4,
                      vbase + (size_t)d * JDIM + k0 + seg * 4);
            }
        }
        asm volatile("cp.async.commit_group;\n");
    };

    // issue tile-0 staging first: latency hides under mb/Q/tri loads
    stage(0, 0);

    if (tid < 96)
        ((float4*)mb)[tid] = *(const float4*)(g_mb + (size_t)i * JDIM + tid * 4);

    // Q fragments: slot16 storage -> one LDG.128 per chunk-pair per row
    uint32_t qa[2][4][4];
    #pragma unroll
    for (int mi = 0; mi < 2; ++mi) {
        int qr = w * 32 + mi * 16 + g;
        const float* p0 = g_qkvg + ((size_t)i * JDIM + qr) * 512 + h * HD;
        const float* p1 = p0 + 8 * 512;
        #pragma unroll
        for (int P = 0; P < 2; ++P) {
            uint4 u0 = *(const uint4*)(p0 + P * 16 + 4 * t);
            uint4 u1 = *(const uint4*)(p1 + P * 16 + 4 * t);
            qa[mi][2*P  ][0] = u0.x; qa[mi][2*P  ][2] = u0.y;
            qa[mi][2*P+1][0] = u0.z; qa[mi][2*P+1][2] = u0.w;
            qa[mi][2*P  ][1] = u1.x; qa[mi][2*P  ][3] = u1.y;
            qa[mi][2*P+1][1] = u1.z; qa[mi][2*P+1][3] = u1.w;
        }
    }

    float l[2][2] = { {0.f, 0.f}, {0.f, 0.f} };
    float o[2][4][4];
    #pragma unroll
    for (int mi = 0; mi < 2; ++mi)
        #pragma unroll
        for (int nt = 0; nt < 4; ++nt)
            #pragma unroll
            for (int j = 0; j < 4; ++j) o[mi][nt][j] = 0.0f;

    const float* tb = g_tri + (size_t)h * NPIX;

    for (int kt = 0; kt < 6; ++kt) {
        const int k0 = kt * 64;
        const int st = kt & 1;

        // S init = tri bias (permv layout -> LDG.128 fills two chunks)
        float s[2][8][4];
        #pragma unroll
        for (int mi = 0; mi < 2; ++mi) {
            const float* t0 = tb + (size_t)(w * 32 + mi * 16 + g) * JDIM + k0;
            const float* t1 = t0 + 8 * JDIM;
            #pragma unroll
            for (int P = 0; P < 4; ++P) {
                float4 a = *(const float4*)(t0 + P * 16 + 4 * t);
                float4 b = *(const float4*)(t1 + P * 16 + 4 * t);
                s[mi][2*P  ][0] = a.x; s[mi][2*P  ][1] = a.y;
                s[mi][2*P+1][0] = a.z; s[mi][2*P+1][1] = a.w;
                s[mi][2*P  ][2] = b.x; s[mi][2*P  ][3] = b.y;
                s[mi][2*P+1][2] = b.z; s[mi][2*P+1][3] = b.w;
            }
        }

        asm volatile("cp.async.wait_group 0;\n");
        __syncthreads();
        if (kt < 5) stage(st ^ 1, k0 + 64);

        // + mask bias (LDS.128 covers two chunks), S += Q K^T
        #pragma unroll
        for (int P = 0; P < 4; ++P) {
            float4 mv = *(const float4*)&mb[k0 + P * 16 + 4 * t];
            #pragma unroll
            for (int mi = 0; mi < 2; ++mi) {
                s[mi][2*P  ][0] += mv.x; s[mi][2*P  ][1] += mv.y;
                s[mi][2*P  ][2] += mv.x; s[mi][2*P  ][3] += mv.y;
                s[mi][2*P+1][0] += mv.z; s[mi][2*P+1][1] += mv.w;
                s[mi][2*P+1][2] += mv.z; s[mi][2*P+1][3] += mv.w;
            }
        }
        #pragma unroll
        for (int nt = 0; nt < 8; ++nt) {
            const uint32_t* krow = Ks + (st * 64 + nt * 8 + g) * KS_W;
            #pragma unroll
            for (int P = 0; P < 2; ++P) {
                uint4 bp = *(const uint4*)(krow + P * 16 + 4 * t);
                mma8(s[0][nt], qa[0][2*P  ], bp.x, bp.y);
                mma8(s[0][nt], qa[0][2*P+1], bp.z, bp.w);
                mma8(s[1][nt], qa[1][2*P  ], bp.x, bp.y);
                mma8(s[1][nt], qa[1][2*P+1], bp.z, bp.w);
            }
        }

        // p = exp2(s); accumulate l (ex2 saturates masked scores to 0)
        #pragma unroll
        for (int mi = 0; mi < 2; ++mi)
            #pragma unroll
            for (int nt = 0; nt < 8; ++nt) {
                s[mi][nt][0] = ex2(s[mi][nt][0]);
                s[mi][nt][1] = ex2(s[mi][nt][1]);
                s[mi][nt][2] = ex2(s[mi][nt][2]);
                s[mi][nt][3] = ex2(s[mi][nt][3]);
                l[mi][0] += s[mi][nt][0] + s[mi][nt][1];
                l[mi][1] += s[mi][nt][2] + s[mi][nt][3];
            }

        // O += P V (one LDS.128 -> 4 MMAs; raw fp32 bits as tf32)
        #pragma unroll
        for (int PP = 0; PP < 4; ++PP) {
            uint32_t pa0a[4], pa0b[4], pa1a[4], pa1b[4];
            int k0c = 2 * PP, k1c = 2 * PP + 1;
            pa0a[0] = __float_as_uint(s[0][k0c][0]); pa0a[1] = __float_as_uint(s[0][k0c][2]);
            pa0a[2] = __float_as_uint(s[0][k0c][1]); pa0a[3] = __float_as_uint(s[0][k0c][3]);
            pa0b[0] = __float_as_uint(s[0][k1c][0]); pa0b[1] = __float_as_uint(s[0][k1c][2]);
            pa0b[2] = __float_as_uint(s[0][k1c][1]); pa0b[3] = __float_as_uint(s[0][k1c][3]);
            pa1a[0] = __float_as_uint(s[1][k0c][0]); pa1a[1] = __float_as_uint(s[1][k0c][2]);
            pa1a[2] = __float_as_uint(s[1][k0c][1]); pa1a[3] = __float_as_uint(s[1][k0c][3]);
            pa1b[0] = __float_as_uint(s[1][k1c][0]); pa1b[1] = __float_as_uint(s[1][k1c][2]);
            pa1b[2] = __float_as_uint(s[1][k1c][1]); pa1b[3] = __float_as_uint(s[1][k1c][3]);
            #pragma unroll
            for (int nt = 0; nt < 4; ++nt) {
                uint4 bp = *(const uint4*)(Vt + (st * 32 + nt * 8 + g) * VT_W + PP * 16 + 4 * t);
                mma8(o[0][nt], pa0a, bp.x, bp.y);
                mma8(o[0][nt], pa0b, bp.z, bp.w);
                mma8(o[1][nt], pa1a, bp.x, bp.y);
                mma8(o[1][nt], pa1b, bp.z, bp.w);
            }
        }
    }

    // epilogue: reduce l, normalize, gate, store natural tf32 bits (coalesced)
    #pragma unroll
    for (int mi = 0; mi < 2; ++mi) {
        float l0 = l[mi][0], l1 = l[mi][1];
        l0 += __shfl_xor_sync(0xffffffffu, l0, 1);
        l0 += __shfl_xor_sync(0xffffffffu, l0, 2);
        l1 += __shfl_xor_sync(0xffffffffu, l1, 1);
        l1 += __shfl_xor_sync(0xffffffffu, l1, 2);
        float inv0 = 1.0f / l0, inv1 = 1.0f / l1;

        int qr = w * 32 + mi * 16 + g;
        size_t pix0 = (size_t)i * JDIM + qr;
        size_t pix1 = pix0 + 8;
        const float* gt0 = g_qkvg + pix0 * 512 + 384 + h * HD;
        const float* gt1 = g_qkvg + pix1 * 512 + 384 + h * HD;
        float* o0 = g_og + pix0 * CH + h * HD;
        float* o1 = g_og + pix1 * CH + h * HD;
        #pragma unroll
        for (int nt = 0; nt < 4; ++nt) {
            int d = nt * 8 + 2 * t;
            float2 gv0 = *(const float2*)(gt0 + d);
            float2 gv1 = *(const float2*)(gt1 + d);
            float2 r0, r1;
            r0.x = __uint_as_float(f2tf(o[mi][nt][0] * inv0 * (1.0f / (1.0f + __expf(-gv0.x)))));
            r0.y = __uint_as_float(f2tf(o[mi][nt][1] * inv0 * (1.0f / (1.0f + __expf(-gv0.y)))));
            r1.x = __uint_as_float(f2tf(o[mi][nt][2] * inv1 * (1.0f / (1.0f + __expf(-gv1.x)))));
            r1.y = __uint_as_float(f2tf(o[mi][nt][3] * inv1 * (1.0f / (1.0f + __expf(-gv1.y)))));
            *(float2*)(o0 + d) = r0;
            *(float2*)(o1 + d) = r1;
        }
    }
}

// ---------------------------------------------------------------------------
// Launch.  Inputs: x, mask, ln_w, ln_b, w_tri, wq, wk, wv, wg, bg, wo, bo
// ---------------------------------------------------------------------------
extern "C" void kernel_launch(void* const* d_in, const int* in_sizes, int n_in,
                              void* d_out, int out_size) {
    const float* x     = (const float*)d_in[0];
    const float* mask  = (const float*)d_in[1];
    const float* ln_w  = (const float*)d_in[2];
    const float* ln_b  = (const float*)d_in[3];
    const float* w_tri = (const float*)d_in[4];
    const float* bg    = (const float*)d_in[9];
    const float* bo    = (const float*)d_in[11];
    float* out = (float*)d_out;

    static bool attr_done = false;
    if (!attr_done) {
        cudaFuncSetAttribute(proj_kernel,
                             cudaFuncAttributeMaxDynamicSharedMemorySize,
                             (int)SMEM_PROJ);
        cudaFuncSetAttribute(attn_mma,
                             cudaFuncAttributeMaxDynamicSharedMemorySize,
                             (int)SMEM_ATTN);
        attr_done = true;
    }

    prepw_kernel<<<5, 128>>>((const float*)d_in[5], (const float*)d_in[6],
                             (const float*)d_in[7], (const float*)d_in[8],
                             (const float*)d_in[10]);
    maskb_kernel<<<(NPIX + 255) / 256, 256>>>(mask);

    // fused LN + tri + q,k,v,g projections
    proj_kernel<<<NPIX / 256, 512, SMEM_PROJ>>>(0, 4, bg,
                                                x, ln_w, ln_b, w_tri,
                                                nullptr, 0);

    // attention (tri + mask bias, gating fused; one block per (h,i))
    attn_mma<<<dim3(NH, IDIM), 384, SMEM_ATTN>>>();

    // output projection
    proj_kernel<<<NPIX / 256, 512, SMEM_PROJ>>>(4, 1, bo,
                                                nullptr, nullptr, nullptr, nullptr,
                                                out, 1);
}

// round 14
// speedup vs baseline: 1.0190x; 1.0190x over previous
#include <cuda_runtime.h>
#include <cstdint>

constexpr int IDIM = 384;
constexpr int JDIM = 384;
constexpr int NPIX = IDIM * JDIM;      // 147456
constexpr int CH   = 128;
constexpr int NH   = 4;
constexpr int HD   = 32;
constexpr float LN_EPS = 1e-5f;
constexpr float QSCALE = 0.17677669529663687f;  // 1/sqrt(32)
constexpr float LOG2E  = 1.4426950408889634f;

// Static device scratch
__device__ float g_qkvg[(size_t)NPIX * 512];   // q|k|-|g (q,k tf32 slot16-interleaved, k rows perm8'd, q pre-scaled; g fp32)
__device__ float g_vt[(size_t)IDIM * NH * HD * JDIM];  // V^T: [i][h][d][permv(j)], tf32 bits
__device__ float g_tri[(size_t)NH * NPIX];     // tri bias * log2e, k-index permv'd
__device__ float g_mb[(size_t)NPIX];           // 1e9*log2e*(mask-1), k-index permv'd
__device__ float g_og[(size_t)NPIX * CH];      // gated attn out, natural, tf32 bits
__device__ uint32_t g_wt[5][128][128];         // transposed tf32 weights, k slot16'd; wq/wk N-cols slot16'd

// ---------------------------------------------------------------------------
__device__ __forceinline__ uint32_t f2tf(float f) {
    uint32_t u;
    asm("cvt.rna.tf32.f32 %0, %1;" : "=r"(u) : "f"(f));
    return u;
}
__device__ __forceinline__ float ex2(float x) {
    float y;
    asm("ex2.approx.f32 %0, %1;" : "=f"(y) : "f"(x));
    return y;
}
__device__ __forceinline__ void mma8(float* d, const uint32_t* a,
                                     uint32_t b0, uint32_t b1) {
    asm volatile(
        "mma.sync.aligned.m16n8k8.row.col.f32.tf32.tf32.f32 "
        "{%0,%1,%2,%3}, {%4,%5,%6,%7}, {%8,%9}, {%0,%1,%2,%3};\n"
        : "+f"(d[0]), "+f"(d[1]), "+f"(d[2]), "+f"(d[3])
        : "r"(a[0]), "r"(a[1]), "r"(a[2]), "r"(a[3]), "r"(b0), "r"(b1));
}
__device__ __forceinline__ void cpa16(void* dst, const void* src) {
    unsigned d = (unsigned)__cvta_generic_to_shared(dst);
    asm volatile("cp.async.cg.shared.global [%0], [%1], 16;\n"
                 :: "r"(d), "l"(src));
}
// pair-interleave within groups of 8 (== mma fragment slot map)
__device__ __forceinline__ int perm8(int x) {
    return (x & ~7) | (((x & 3) << 1) | ((x >> 2) & 1));
}
// dim d -> storage pos: chunk-PAIR fragment words contiguous (16B = 4 frag words)
__device__ __forceinline__ int slot16(int x) {
    int w = x & 15, c = w >> 3, v = w & 7;
    return (x & ~15) | ((v & 3) << 2) | (c << 1) | (v >> 2);
}
// key j -> storage col: sigma within 8, then chunk-pair interleave
__device__ __forceinline__ int permv(int j) {
    int p8 = perm8(j) & 7;
    int c  = (j >> 3) & 1;
    return (j & ~15) | ((p8 >> 1) << 2) | (c << 1) | (p8 & 1);
}

// ---------------------------------------------------------------------------
// Kernel A: merged one-shot prep. Blocks 0-4: weight transpose + tf32 +
// slot16 perms (+ wq scale). Blocks 5..580: permv'd mask-bias rows.
// ---------------------------------------------------------------------------
__global__ void prep_kernel(const float* __restrict__ wq,
                            const float* __restrict__ wk,
                            const float* __restrict__ wv,
                            const float* __restrict__ wg,
                            const float* __restrict__ wo,
                            const float* __restrict__ mask) {
    if (blockIdx.x < 5) {
        const float* Ws[5] = { wq, wk, wv, wg, wo };
        int wi = blockIdx.x;
        int k  = threadIdx.x & 127;
        if (threadIdx.x >= 128) return;
        float scale = (wi == 0) ? (QSCALE * LOG2E) : 1.0f;
        const float4* src = (const float4*)(Ws[wi] + (size_t)k * 128);
        int pk = slot16(k);
        bool nperm = (wi <= 1);
        #pragma unroll
        for (int c = 0; c < 32; ++c) {
            float4 v = src[c];
            float vv[4] = { v.x, v.y, v.z, v.w };
            #pragma unroll
            for (int e = 0; e < 4; ++e) {
                int n = c * 4 + e;
                int np = nperm ? slot16(n) : n;
                g_wt[wi][np][pk] = f2tf(vv[e] * scale);
            }
        }
    } else {
        int idx = (blockIdx.x - 5) * 256 + threadIdx.x;
        if (idx >= NPIX) return;
        int i = idx / JDIM;
        int j = idx - i * JDIM;
        g_mb[(size_t)i * JDIM + permv(j)] = (1e9f * LOG2E) * (mask[idx] - 1.0f);
    }
}

// ---------------------------------------------------------------------------
// Kernel C: fused {LayerNorm + tri-proj} + tf32 mma projections.
// A and W staged in slot16 k-layout -> mainloop fragment loads are LDS.128
// (each feeding 4 MMAs). PPAD 144 (== 16 mod 32): conflict-free LDS.128.
// W staged via cp.async hidden under epilogue.
// ---------------------------------------------------------------------------
constexpr int PPAD = 144;
constexpr size_t SMEM_PROJ = (size_t)(256 * PPAD + 128 * PPAD + 768) * 4;

__global__ void __launch_bounds__(512) proj_kernel(
        int wbase, int nw, const float* __restrict__ bias,
        const float* __restrict__ X,
        const float* __restrict__ ln_w, const float* __restrict__ ln_b,
        const float* __restrict__ w_tri,
        float* __restrict__ Cext, int amode) {
    extern __shared__ uint32_t smu[];
    uint32_t* Asu = smu;                    // [256][PPAD]
    uint32_t* Wtu = smu + 256 * PPAD;       // [128][PPAD]
    float* lnw  = (float*)(Wtu + 128 * PPAD);
    float* lnb  = lnw + 128;
    float* wtri = lnb + 128;

    const int tid = threadIdx.x;
    const int bm  = blockIdx.x * 256;

    // prefetch W0 while A is being staged
    {
        int n = tid >> 2, q4 = tid & 3;
        const float4* src = (const float4*)&g_wt[wbase][n][q4 * 32];
        uint32_t* dst = Wtu + n * PPAD + q4 * 32;
        #pragma unroll
        for (int c = 0; c < 8; ++c)
            cpa16(dst + c * 4, src + c);
        asm volatile("cp.async.commit_group;\n");
    }

    if (amode == 0) {
        if (tid < 32)        ((float4*)lnw)[tid]       = ((const float4*)ln_w)[tid];
        else if (tid < 64)   ((float4*)lnb)[tid - 32]  = ((const float4*)ln_b)[tid - 32];
        else if (tid < 192)  ((float4*)wtri)[tid - 64] = ((const float4*)w_tri)[tid - 64];
    }
    __syncthreads();

    // ---- stage A (slot16 k-layout) ----
    {
        int r = tid >> 1, half = tid & 1;
        int gw = bm + r;
        uint32_t* arow = Asu + r * PPAD;

        if (amode == 0) {
            const float4* xr = (const float4*)(X + (size_t)gw * 128 + half * 64);
            float s = 0.f, ss = 0.f;
            #pragma unroll
            for (int c = 0; c < 16; ++c) {
                float4 v = xr[c];
                s  += v.x + v.y + v.z + v.w;
                ss += v.x * v.x + v.y * v.y + v.z * v.z + v.w * v.w;
            }
            s  += __shfl_xor_sync(0xffffffffu, s, 1);
            ss += __shfl_xor_sync(0xffffffffu, ss, 1);
            float mu = s * (1.0f / 128.0f);
            float rs = rsqrtf(fmaxf(ss * (1.0f / 128.0f) - mu * mu, 0.f) + LN_EPS);

            float th0 = 0.f, th1 = 0.f, th2 = 0.f, th3 = 0.f;
            #pragma unroll
            for (int c = 0; c < 16; ++c) {
                float4 v = xr[c];
                float vs[4] = { v.x, v.y, v.z, v.w };
                #pragma unroll
                for (int e = 0; e < 4; ++e) {
                    int ch = half * 64 + c * 4 + e;
                    float xn = (vs[e] - mu) * rs * lnw[ch] + lnb[ch];
                    float4 wt = ((const float4*)wtri)[ch];
                    th0 += xn * wt.x; th1 += xn * wt.y;
                    th2 += xn * wt.z; th3 += xn * wt.w;
                    arow[slot16(ch)] = f2tf(xn);
                }
            }
            th0 += __shfl_xor_sync(0xffffffffu, th0, 1);
            th1 += __shfl_xor_sync(0xffffffffu, th1, 1);
            th2 += __shfl_xor_sync(0xffffffffu, th2, 1);
            th3 += __shfl_xor_sync(0xffffffffu, th3, 1);
            if (half == 0) {
                size_t dst = (size_t)permv(gw);
                g_tri[0 * (size_t)NPIX + dst] = th0 * LOG2E;
                g_tri[1 * (size_t)NPIX + dst] = th1 * LOG2E;
                g_tri[2 * (size_t)NPIX + dst] = th2 * LOG2E;
                g_tri[3 * (size_t)NPIX + dst] = th3 * LOG2E;
            }
        } else {
            const float4* xr = (const float4*)(g_og + (size_t)gw * 128 + half * 64);
            #pragma unroll
            for (int c = 0; c < 16; ++c) {
                float4 v = xr[c];
                int ch = half * 64 + c * 4;
                arow[slot16(ch + 0)] = __float_as_uint(v.x);
                arow[slot16(ch + 1)] = __float_as_uint(v.y);
                arow[slot16(ch + 2)] = __float_as_uint(v.z);
                arow[slot16(ch + 3)] = __float_as_uint(v.w);
            }
        }
    }

    const int w = tid >> 5, lane = tid & 31;
    const int g = lane >> 2, t = lane & 3;
    const int wm = w >> 1, wn = w & 1;

    for (int wi = 0; wi < nw; ++wi) {
        asm volatile("cp.async.wait_group 0;\n");
        __syncthreads();

        float acc[2][8][4];
        #pragma unroll
        for (int mi = 0; mi < 2; ++mi)
            #pragma unroll
            for (int nt = 0; nt < 8; ++nt)
                #pragma unroll
                for (int j = 0; j < 4; ++j) acc[mi][nt][j] = 0.0f;

        // kk-pairs: one LDS.128 per operand feeds 2 chunks
        #pragma unroll
        for (int P = 0; P < 8; ++P) {
            uint32_t a[2][2][4];   // [mi][chunk]
            #pragma unroll
            for (int mi = 0; mi < 2; ++mi) {
                int rb = wm * 32 + mi * 16;
                uint4 u0 = *(const uint4*)&Asu[(rb + g) * PPAD + P * 16 + 4 * t];
                uint4 u1 = *(const uint4*)&Asu[(rb + g + 8) * PPAD + P * 16 + 4 * t];
                a[mi][0][0] = u0.x; a[mi][0][2] = u0.y;
                a[mi][1][0] = u0.z; a[mi][1][2] = u0.w;
                a[mi][0][1] = u1.x; a[mi][0][3] = u1.y;
                a[mi][1][1] = u1.z; a[mi][1][3] = u1.w;
            }
            #pragma unroll
            for (int nt = 0; nt < 8; ++nt) {
                uint4 bp = *(const uint4*)&Wtu[(wn * 64 + nt * 8 + g) * PPAD + P * 16 + 4 * t];
                mma8(acc[0][nt], a[0][0], bp.x, bp.y);
                mma8(acc[0][nt], a[0][1], bp.z, bp.w);
                mma8(acc[1][nt], a[1][0], bp.x, bp.y);
                mma8(acc[1][nt], a[1][1], bp.z, bp.w);
            }
        }

        __syncthreads();   // all warps done reading Wtu
        if (wi + 1 < nw) { // prefetch next W; copy hides under the epilogue
            int n = tid >> 2, q4 = tid & 3;
            const float4* src = (const float4*)&g_wt[wbase + wi + 1][n][q4 * 32];
            uint32_t* dst = Wtu + n * PPAD + q4 * 32;
            #pragma unroll
            for (int c = 0; c < 8; ++c)
                cpa16(dst + c * 4, src + c);
            asm volatile("cp.async.commit_group;\n");
        }

        // epilogue
        #pragma unroll
        for (int mi = 0; mi < 2; ++mi) {
            int row0 = bm + wm * 32 + mi * 16 + g;
            int row1 = row0 + 8;
            int i0 = row0 / JDIM, j0 = row0 - i0 * JDIM;
            int i1 = row1 / JDIM, j1 = row1 - i1 * JDIM;
            int pj0 = permv(j0), pj1 = permv(j1);
            #pragma unroll
            for (int nt = 0; nt < 8; ++nt) {
                int col = wn * 64 + nt * 8 + 2 * t;
                float v0 = acc[mi][nt][0], v1 = acc[mi][nt][1];
                float v2 = acc[mi][nt][2], v3 = acc[mi][nt][3];
                if (amode == 0) {
                    if (wi <= 1) {          // q/k: cols already slot16 order
                        int r0 = (wi == 1) ? perm8(row0) : row0;
                        int r1 = (wi == 1) ? perm8(row1) : row1;
                        float2 a0 = { __uint_as_float(f2tf(v0)), __uint_as_float(f2tf(v1)) };
                        float2 a1 = { __uint_as_float(f2tf(v2)), __uint_as_float(f2tf(v3)) };
                        *(float2*)(g_qkvg + (size_t)r0 * 512 + wi * 128 + col) = a0;
                        *(float2*)(g_qkvg + (size_t)r1 * 512 + wi * 128 + col) = a1;
                    } else if (wi == 2) {   // v: transposed tf32 into g_vt, permv cols
                        int hh = col >> 5, d0 = col & 31;
                        size_t b0 = ((size_t)(i0 * NH + hh) * HD + d0) * JDIM;
                        size_t b1 = ((size_t)(i1 * NH + hh) * HD + d0) * JDIM;
                        g_vt[b0 + pj0]        = __uint_as_float(f2tf(v0));
                        g_vt[b0 + JDIM + pj0] = __uint_as_float(f2tf(v1));
                        g_vt[b1 + pj1]        = __uint_as_float(f2tf(v2));
                        g_vt[b1 + JDIM + pj1] = __uint_as_float(f2tf(v3));
                    } else {                // g: + bias, fp32 natural
                        float2 bb = *(const float2*)(bias + col);
                        float2 a0 = { v0 + bb.x, v1 + bb.y };
                        float2 a1 = { v2 + bb.x, v3 + bb.y };
                        *(float2*)(g_qkvg + (size_t)row0 * 512 + 384 + col) = a0;
                        *(float2*)(g_qkvg + (size_t)row1 * 512 + 384 + col) = a1;
                    }
                } else {
                    float2 bb = *(const float2*)(bias + col);
                    float2 a0 = { v0 + bb.x, v1 + bb.y };
                    float2 a1 = { v2 + bb.x, v3 + bb.y };
                    *(float2*)(Cext + (size_t)row0 * 128 + col) = a0;
                    *(float2*)(Cext + (size_t)row1 * 128 + col) = a1;
                }
            }
        }
    }
}

// ---------------------------------------------------------------------------
// Kernel D: tf32 mma flash attention (R12 structure). 192 threads, 6 warps
// x 32 q-rows, q-tile 192, 2 blocks/SM. All fragment loads 128-bit.
// Mask-bias add hoisted above the cp.async wait (off the critical path).
// ---------------------------------------------------------------------------
constexpr int KS_W = 80;
constexpr int VT_W = 80;
constexpr size_t SMEM_ATTN = (size_t)(2 * 64 * KS_W + 2 * 32 * VT_W + 384) * 4;

__global__ void __launch_bounds__(192, 2) attn_mma() {
    extern __shared__ uint32_t sm[];
    uint32_t* Ks = sm;                    // [2][64][KS_W]
    uint32_t* Vt = sm + 2 * 64 * KS_W;    // [2][32][VT_W]
    float*    mb = (float*)(Vt + 2 * 32 * VT_W);

    const int qt  = blockIdx.x;       // 0..1
    const int h   = blockIdx.y;       // 0..3
    const int i   = blockIdx.z;       // 0..383
    const int tid = threadIdx.x;
    const int w = tid >> 5, lane = tid & 31;
    const int g = lane >> 2, t = lane & 3;
    const int q0 = qt * 192;

    const float* kbase = g_qkvg + ((size_t)i * JDIM) * 512 + 128 + h * HD;
    const float* vbase = g_vt + (size_t)(i * NH + h) * HD * JDIM;

    auto stage = [&](int st, int k0) {
        #pragma unroll
        for (int c = tid; c < 1024; c += 192) {
            if (c < 512) {
                int r = c >> 3, seg = c & 7;
                cpa16(Ks + (st * 64 + r) * KS_W + seg * 4,
                      kbase + (size_t)(k0 + r) * 512 + seg * 4);
            } else {
                int vc = c - 512;
                int d = vc >> 4, seg = vc & 15;
                cpa16(Vt + (st * 32 + d) * VT_W + seg * 4,
                      vbase + (size_t)d * JDIM + k0 + seg * 4);
            }
        }
        asm volatile("cp.async.commit_group;\n");
    };

    // issue tile-0 staging first; its latency hides under the prologue loads
    stage(0, 0);

    if (tid < 96)
        ((float4*)mb)[tid] = *(const float4*)(g_mb + (size_t)i * JDIM + tid * 4);

    // Q fragments: slot16 storage -> one LDG.128 per chunk-pair per row
    uint32_t qa[2][4][4];
    #pragma unroll
    for (int mi = 0; mi < 2; ++mi) {
        int qr = q0 + w * 32 + mi * 16 + g;
        const float* p0 = g_qkvg + ((size_t)i * JDIM + qr) * 512 + h * HD;
        const float* p1 = p0 + 8 * 512;
        #pragma unroll
        for (int P = 0; P < 2; ++P) {
            uint4 u0 = *(const uint4*)(p0 + P * 16 + 4 * t);
            uint4 u1 = *(const uint4*)(p1 + P * 16 + 4 * t);
            qa[mi][2*P  ][0] = u0.x; qa[mi][2*P  ][2] = u0.y;
            qa[mi][2*P+1][0] = u0.z; qa[mi][2*P+1][2] = u0.w;
            qa[mi][2*P  ][1] = u1.x; qa[mi][2*P  ][3] = u1.y;
            qa[mi][2*P+1][1] = u1.z; qa[mi][2*P+1][3] = u1.w;
        }
    }
    __syncthreads();   // mb visible to all threads (enables pre-wait mask add)

    float l[2][2] = { {0.f, 0.f}, {0.f, 0.f} };
    float o[2][4][4];
    #pragma unroll
    for (int mi = 0; mi < 2; ++mi)
        #pragma unroll
        for (int nt = 0; nt < 4; ++nt)
            #pragma unroll
            for (int j = 0; j < 4; ++j) o[mi][nt][j] = 0.0f;

    const float* tb = g_tri + (size_t)h * NPIX;

    for (int kt = 0; kt < 6; ++kt) {
        const int k0 = kt * 64;
        const int st = kt & 1;

        // S init = tri bias + mask bias, all BEFORE the cp wait
        float s[2][8][4];
        #pragma unroll
        for (int mi = 0; mi < 2; ++mi) {
            const float* t0 = tb + (size_t)(q0 + w * 32 + mi * 16 + g) * JDIM + k0;
            const float* t1 = t0 + 8 * JDIM;
            #pragma unroll
            for (int P = 0; P < 4; ++P) {
                float4 a = *(const float4*)(t0 + P * 16 + 4 * t);
                float4 b = *(const float4*)(t1 + P * 16 + 4 * t);
                s[mi][2*P  ][0] = a.x; s[mi][2*P  ][1] = a.y;
                s[mi][2*P+1][0] = a.z; s[mi][2*P+1][1] = a.w;
                s[mi][2*P  ][2] = b.x; s[mi][2*P  ][3] = b.y;
                s[mi][2*P+1][2] = b.z; s[mi][2*P+1][3] = b.w;
            }
        }
        #pragma unroll
        for (int P = 0; P < 4; ++P) {
            float4 mv = *(const float4*)&mb[k0 + P * 16 + 4 * t];
            #pragma unroll
            for (int mi = 0; mi < 2; ++mi) {
                s[mi][2*P  ][0] += mv.x; s[mi][2*P  ][1] += mv.y;
                s[mi][2*P  ][2] += mv.x; s[mi][2*P  ][3] += mv.y;
                s[mi][2*P+1][0] += mv.z; s[mi][2*P+1][1] += mv.w;
                s[mi][2*P+1][2] += mv.z; s[mi][2*P+1][3] += mv.w;
            }
        }

        asm volatile("cp.async.wait_group 0;\n");
        __syncthreads();
        if (kt < 5) stage(st ^ 1, k0 + 64);

        // S += Q K^T (one LDS.128 -> 4 MMAs)
        #pragma unroll
        for (int nt = 0; nt < 8; ++nt) {
            const uint32_t* krow = Ks + (st * 64 + nt * 8 + g) * KS_W;
            #pragma unroll
            for (int P = 0; P < 2; ++P) {
                uint4 bp = *(const uint4*)(krow + P * 16 + 4 * t);
                mma8(s[0][nt], qa[0][2*P  ], bp.x, bp.y);
                mma8(s[0][nt], qa[0][2*P+1], bp.z, bp.w);
                mma8(s[1][nt], qa[1][2*P  ], bp.x, bp.y);
                mma8(s[1][nt], qa[1][2*P+1], bp.z, bp.w);
            }
        }

        // p = exp2(s); accumulate l (ex2 saturates masked scores to 0)
        #pragma unroll
        for (int mi = 0; mi < 2; ++mi)
            #pragma unroll
            for (int nt = 0; nt < 8; ++nt) {
                s[mi][nt][0] = ex2(s[mi][nt][0]);
                s[mi][nt][1] = ex2(s[mi][nt][1]);
                s[mi][nt][2] = ex2(s[mi][nt][2]);
                s[mi][nt][3] = ex2(s[mi][nt][3]);
                l[mi][0] += s[mi][nt][0] + s[mi][nt][1];
                l[mi][1] += s[mi][nt][2] + s[mi][nt][3];
            }

        // O += P V (one LDS.128 -> 4 MMAs; raw fp32 bits as tf32)
        #pragma unroll
        for (int PP = 0; PP < 4; ++PP) {
            uint32_t pa0a[4], pa0b[4], pa1a[4], pa1b[4];
            int k0c = 2 * PP, k1c = 2 * PP + 1;
            pa0a[0] = __float_as_uint(s[0][k0c][0]); pa0a[1] = __float_as_uint(s[0][k0c][2]);
            pa0a[2] = __float_as_uint(s[0][k0c][1]); pa0a[3] = __float_as_uint(s[0][k0c][3]);
            pa0b[0] = __float_as_uint(s[0][k1c][0]); pa0b[1] = __float_as_uint(s[0][k1c][2]);
            pa0b[2] = __float_as_uint(s[0][k1c][1]); pa0b[3] = __float_as_uint(s[0][k1c][3]);
            pa1a[0] = __float_as_uint(s[1][k0c][0]); pa1a[1] = __float_as_uint(s[1][k0c][2]);
            pa1a[2] = __float_as_uint(s[1][k0c][1]); pa1a[3] = __float_as_uint(s[1][k0c][3]);
            pa1b[0] = __float_as_uint(s[1][k1c][0]); pa1b[1] = __float_as_uint(s[1][k1c][2]);
            pa1b[2] = __float_as_uint(s[1][k1c][1]); pa1b[3] = __float_as_uint(s[1][k1c][3]);
            #pragma unroll
            for (int nt = 0; nt < 4; ++nt) {
                uint4 bp = *(const uint4*)(Vt + (st * 32 + nt * 8 + g) * VT_W + PP * 16 + 4 * t);
                mma8(o[0][nt], pa0a, bp.x, bp.y);
                mma8(o[0][nt], pa0b, bp.z, bp.w);
                mma8(o[1][nt], pa1a, bp.x, bp.y);
                mma8(o[1][nt], pa1b, bp.z, bp.w);
            }
        }
    }

    // epilogue: reduce l, normalize, gate, store natural tf32 bits (coalesced)
    #pragma unroll
    for (int mi = 0; mi < 2; ++mi) {
        float l0 = l[mi][0], l1 = l[mi][1];
        l0 += __shfl_xor_sync(0xffffffffu, l0, 1);
        l0 += __shfl_xor_sync(0xffffffffu, l0, 2);
        l1 += __shfl_xor_sync(0xffffffffu, l1, 1);
        l1 += __shfl_xor_sync(0xffffffffu, l1, 2);
        float inv0 = 1.0f / l0, inv1 = 1.0f / l1;

        int qr = q0 + w * 32 + mi * 16 + g;
        size_t pix0 = (size_t)i * JDIM + qr;
        size_t pix1 = pix0 + 8;
        const float* gt0 = g_qkvg + pix0 * 512 + 384 + h * HD;
        const float* gt1 = g_qkvg + pix1 * 512 + 384 + h * HD;
        float* o0 = g_og + pix0 * CH + h * HD;
        float* o1 = g_og + pix1 * CH + h * HD;
        #pragma unroll
        for (int nt = 0; nt < 4; ++nt) {
            int d = nt * 8 + 2 * t;
            float2 gv0 = *(const float2*)(gt0 + d);
            float2 gv1 = *(const float2*)(gt1 + d);
            float2 r0, r1;
            r0.x = __uint_as_float(f2tf(o[mi][nt][0] * inv0 * (1.0f / (1.0f + __expf(-gv0.x)))));
            r0.y = __uint_as_float(f2tf(o[mi][nt][1] * inv0 * (1.0f / (1.0f + __expf(-gv0.y)))));
            r1.x = __uint_as_float(f2tf(o[mi][nt][2] * inv1 * (1.0f / (1.0f + __expf(-gv1.x)))));
            r1.y = __uint_as_float(f2tf(o[mi][nt][3] * inv1 * (1.0f / (1.0f + __expf(-gv1.y)))));
            *(float2*)(o0 + d) = r0;
            *(float2*)(o1 + d) = r1;
        }
    }
}

// ---------------------------------------------------------------------------
// Launch.  Inputs: x, mask, ln_w, ln_b, w_tri, wq, wk, wv, wg, bg, wo, bo
// ---------------------------------------------------------------------------
extern "C" void kernel_launch(void* const* d_in, const int* in_sizes, int n_in,
                              void* d_out, int out_size) {
    const float* x     = (const float*)d_in[0];
    const float* mask  = (const float*)d_in[1];
    const float* ln_w  = (const float*)d_in[2];
    const float* ln_b  = (const float*)d_in[3];
    const float* w_tri = (const float*)d_in[4];
    const float* bg    = (const float*)d_in[9];
    const float* bo    = (const float*)d_in[11];
    float* out = (float*)d_out;

    static bool attr_done = false;
    if (!attr_done) {
        cudaFuncSetAttribute(proj_kernel,
                             cudaFuncAttributeMaxDynamicSharedMemorySize,
                             (int)SMEM_PROJ);
        cudaFuncSetAttribute(attn_mma,
                             cudaFuncAttributeMaxDynamicSharedMemorySize,
                             (int)SMEM_ATTN);
        attr_done = true;
    }

    // merged weight + mask prep (blocks 0-4 weights, 5+ mask rows)
    prep_kernel<<<5 + (NPIX + 255) / 256, 256>>>(
        (const float*)d_in[5], (const float*)d_in[6], (const float*)d_in[7],
        (const float*)d_in[8], (const float*)d_in[10], mask);

    // fused LN + tri + q,k,v,g projections
    proj_kernel<<<NPIX / 256, 512, SMEM_PROJ>>>(0, 4, bg,
                                                x, ln_w, ln_b, w_tri,
                                                nullptr, 0);

    // attention (tri + mask bias, gating fused)
    attn_mma<<<dim3(2, NH, IDIM), 192, SMEM_ATTN>>>();

    // output projection
    proj_kernel<<<NPIX / 256, 512, SMEM_PROJ>>>(4, 1, bo,
                                                nullptr, nullptr, nullptr, nullptr,
                                                out, 1);
}

// round 15
// speedup vs baseline: 1.1018x; 1.0813x over previous
#include <cuda_runtime.h>
#include <cstdint>

constexpr int IDIM = 384;
constexpr int JDIM = 384;
constexpr int NPIX = IDIM * JDIM;      // 147456
constexpr int CH   = 128;
constexpr int NH   = 4;
constexpr int HD   = 32;
constexpr float LN_EPS = 1e-5f;
constexpr float QSCALE = 0.17677669529663687f;  // 1/sqrt(32)
constexpr float LOG2E  = 1.4426950408889634f;

// Static device scratch
__device__ float g_qkvg[(size_t)NPIX * 512];   // q|k|-|g (q,k tf32 slot16-interleaved, k rows perm8'd, q pre-scaled; g fp32)
__device__ float g_vt[(size_t)IDIM * NH * HD * JDIM];  // V^T: [i][h][d][permv(j)], tf32 bits
__device__ float g_tri[(size_t)NH * NPIX];     // tri bias * log2e, k-index permv'd
__device__ float g_mb[(size_t)NPIX];           // 1e9*log2e*(mask-1), k-index permv'd
__device__ float g_og[(size_t)NPIX * CH];      // gated attn out, natural, tf32 bits
__device__ uint32_t g_wt[5][128][128];         // transposed tf32 weights, k slot16'd; wq/wk N-cols slot16'd

// ---------------------------------------------------------------------------
__device__ __forceinline__ uint32_t f2tf(float f) {
    uint32_t u;
    asm("cvt.rna.tf32.f32 %0, %1;" : "=r"(u) : "f"(f));
    return u;
}
__device__ __forceinline__ float ex2(float x) {
    float y;
    asm("ex2.approx.f32 %0, %1;" : "=f"(y) : "f"(x));
    return y;
}
__device__ __forceinline__ void mma8(float* d, const uint32_t* a,
                                     uint32_t b0, uint32_t b1) {
    asm volatile(
        "mma.sync.aligned.m16n8k8.row.col.f32.tf32.tf32.f32 "
        "{%0,%1,%2,%3}, {%4,%5,%6,%7}, {%8,%9}, {%0,%1,%2,%3};\n"
        : "+f"(d[0]), "+f"(d[1]), "+f"(d[2]), "+f"(d[3])
        : "r"(a[0]), "r"(a[1]), "r"(a[2]), "r"(a[3]), "r"(b0), "r"(b1));
}
__device__ __forceinline__ void cpa16(void* dst, const void* src) {
    unsigned d = (unsigned)__cvta_generic_to_shared(dst);
    asm volatile("cp.async.cg.shared.global [%0], [%1], 16;\n"
                 :: "r"(d), "l"(src));
}
// pair-interleave within groups of 8 (== mma fragment slot map)
__device__ __forceinline__ int perm8(int x) {
    return (x & ~7) | (((x & 3) << 1) | ((x >> 2) & 1));
}
// dim d -> storage pos: chunk-PAIR fragment words contiguous (16B = 4 frag words)
__device__ __forceinline__ int slot16(int x) {
    int w = x & 15, c = w >> 3, v = w & 7;
    return (x & ~15) | ((v & 3) << 2) | (c << 1) | (v >> 2);
}
// key j -> storage col: sigma within 8, then chunk-pair interleave
__device__ __forceinline__ int permv(int j) {
    int p8 = perm8(j) & 7;
    int c  = (j >> 3) & 1;
    return (j & ~15) | ((p8 >> 1) << 2) | (c << 1) | (p8 & 1);
}

// ---------------------------------------------------------------------------
// Kernel A: merged one-shot prep. Blocks 0-4: weight transpose + tf32 +
// slot16 perms (+ wq scale). Blocks 5+: permv'd mask-bias rows.
// ---------------------------------------------------------------------------
__global__ void prep_kernel(const float* __restrict__ wq,
                            const float* __restrict__ wk,
                            const float* __restrict__ wv,
                            const float* __restrict__ wg,
                            const float* __restrict__ wo,
                            const float* __restrict__ mask) {
    if (blockIdx.x < 5) {
        const float* Ws[5] = { wq, wk, wv, wg, wo };
        int wi = blockIdx.x;
        if (threadIdx.x >= 128) return;
        int k = threadIdx.x;
        float scale = (wi == 0) ? (QSCALE * LOG2E) : 1.0f;
        const float4* src = (const float4*)(Ws[wi] + (size_t)k * 128);
        int pk = slot16(k);
        bool nperm = (wi <= 1);
        #pragma unroll
        for (int c = 0; c < 32; ++c) {
            float4 v = src[c];
            float vv[4] = { v.x, v.y, v.z, v.w };
            #pragma unroll
            for (int e = 0; e < 4; ++e) {
                int n = c * 4 + e;
                int np = nperm ? slot16(n) : n;
                g_wt[wi][np][pk] = f2tf(vv[e] * scale);
            }
        }
    } else {
        int idx = (blockIdx.x - 5) * 256 + threadIdx.x;
        if (idx >= NPIX) return;
        int i = idx / JDIM;
        int j = idx - i * JDIM;
        g_mb[(size_t)i * JDIM + permv(j)] = (1e9f * LOG2E) * (mask[idx] - 1.0f);
    }
}

// ---------------------------------------------------------------------------
// Kernel C: fused {LayerNorm + tri-proj} + tf32 mma projections.
// Stage-A now packs 16 channels in registers and emits rotated STS.128
// (breaks the 16-way bank conflict of the old per-word slot scatter).
// Mainloop: LDS.128 fragment loads feeding 4 MMAs. PPAD 144.
// ---------------------------------------------------------------------------
constexpr int PPAD = 144;
constexpr size_t SMEM_PROJ = (size_t)(256 * PPAD + 128 * PPAD + 768) * 4;

__global__ void __launch_bounds__(512) proj_kernel(
        int wbase, int nw, const float* __restrict__ bias,
        const float* __restrict__ X,
        const float* __restrict__ ln_w, const float* __restrict__ ln_b,
        const float* __restrict__ w_tri,
        float* __restrict__ Cext, int amode) {
    extern __shared__ uint32_t smu[];
    uint32_t* Asu = smu;                    // [256][PPAD]
    uint32_t* Wtu = smu + 256 * PPAD;       // [128][PPAD]
    float* lnw  = (float*)(Wtu + 128 * PPAD);
    float* lnb  = lnw + 128;
    float* wtri = lnb + 128;

    const int tid = threadIdx.x;
    const int bm  = blockIdx.x * 256;

    // prefetch W0 while A is being staged
    {
        int n = tid >> 2, q4 = tid & 3;
        const float4* src = (const float4*)&g_wt[wbase][n][q4 * 32];
        uint32_t* dst = Wtu + n * PPAD + q4 * 32;
        #pragma unroll
        for (int c = 0; c < 8; ++c)
            cpa16(dst + c * 4, src + c);
        asm volatile("cp.async.commit_group;\n");
    }

    if (amode == 0) {
        if (tid < 32)        ((float4*)lnw)[tid]       = ((const float4*)ln_w)[tid];
        else if (tid < 64)   ((float4*)lnb)[tid - 32]  = ((const float4*)ln_b)[tid - 32];
        else if (tid < 192)  ((float4*)wtri)[tid - 64] = ((const float4*)w_tri)[tid - 64];
    }
    __syncthreads();

    // ---- stage A (slot16 k-layout; packed STS.128 with per-row rotation) ----
    {
        int r = tid >> 1, half = tid & 1;
        int gw = bm + r;
        uint32_t* arow = Asu + r * PPAD + half * 64;
        const int rot = (r >> 1) & 3;

        if (amode == 0) {
            const float4* xr = (const float4*)(X + (size_t)gw * 128 + half * 64);
            float s = 0.f, ss = 0.f;
            #pragma unroll
            for (int c = 0; c < 16; ++c) {
                float4 v = xr[c];
                s  += v.x + v.y + v.z + v.w;
                ss += v.x * v.x + v.y * v.y + v.z * v.z + v.w * v.w;
            }
            s  += __shfl_xor_sync(0xffffffffu, s, 1);
            ss += __shfl_xor_sync(0xffffffffu, ss, 1);
            float mu = s * (1.0f / 128.0f);
            float rs = rsqrtf(fmaxf(ss * (1.0f / 128.0f) - mu * mu, 0.f) + LN_EPS);

            float th0 = 0.f, th1 = 0.f, th2 = 0.f, th3 = 0.f;
            #pragma unroll
            for (int grp = 0; grp < 4; ++grp) {
                float xng[16];
                #pragma unroll
                for (int c4 = 0; c4 < 4; ++c4) {
                    float4 v = xr[grp * 4 + c4];
                    float vs[4] = { v.x, v.y, v.z, v.w };
                    #pragma unroll
                    for (int e = 0; e < 4; ++e) {
                        int ch = half * 64 + grp * 16 + c4 * 4 + e;
                        float xn = (vs[e] - mu) * rs * lnw[ch] + lnb[ch];
                        float4 wt = ((const float4*)wtri)[ch];
                        th0 += xn * wt.x; th1 += xn * wt.y;
                        th2 += xn * wt.z; th3 += xn * wt.w;
                        xng[c4 * 4 + e] = xn;
                    }
                }
                #pragma unroll
                for (int idx = 0; idx < 4; ++idx) {
                    int tp = (idx + rot) & 3;
                    uint4 u = { f2tf(xng[tp]),     f2tf(xng[tp + 4]),
                                f2tf(xng[tp + 8]), f2tf(xng[tp + 12]) };
                    *(uint4*)(arow + grp * 16 + 4 * tp) = u;
                }
            }
            th0 += __shfl_xor_sync(0xffffffffu, th0, 1);
            th1 += __shfl_xor_sync(0xffffffffu, th1, 1);
            th2 += __shfl_xor_sync(0xffffffffu, th2, 1);
            th3 += __shfl_xor_sync(0xffffffffu, th3, 1);
            if (half == 0) {
                size_t dst = (size_t)permv(gw);
                g_tri[0 * (size_t)NPIX + dst] = th0 * LOG2E;
                g_tri[1 * (size_t)NPIX + dst] = th1 * LOG2E;
                g_tri[2 * (size_t)NPIX + dst] = th2 * LOG2E;
                g_tri[3 * (size_t)NPIX + dst] = th3 * LOG2E;
            }
        } else {
            const float4* xr = (const float4*)(g_og + (size_t)gw * 128 + half * 64);
            #pragma unroll
            for (int grp = 0; grp < 4; ++grp) {
                uint32_t xng[16];
                #pragma unroll
                for (int c4 = 0; c4 < 4; ++c4) {
                    float4 v = xr[grp * 4 + c4];
                    xng[c4 * 4 + 0] = __float_as_uint(v.x);
                    xng[c4 * 4 + 1] = __float_as_uint(v.y);
                    xng[c4 * 4 + 2] = __float_as_uint(v.z);
                    xng[c4 * 4 + 3] = __float_as_uint(v.w);
                }
                #pragma unroll
                for (int idx = 0; idx < 4; ++idx) {
                    int tp = (idx + rot) & 3;
                    uint4 u = { xng[tp], xng[tp + 4], xng[tp + 8], xng[tp + 12] };
                    *(uint4*)(arow + grp * 16 + 4 * tp) = u;
                }
            }
        }
    }

    const int w = tid >> 5, lane = tid & 31;
    const int g = lane >> 2, t = lane & 3;
    const int wm = w >> 1, wn = w & 1;

    for (int wi = 0; wi < nw; ++wi) {
        asm volatile("cp.async.wait_group 0;\n");
        __syncthreads();

        float acc[2][8][4];
        #pragma unroll
        for (int mi = 0; mi < 2; ++mi)
            #pragma unroll
            for (int nt = 0; nt < 8; ++nt)
                #pragma unroll
                for (int j = 0; j < 4; ++j) acc[mi][nt][j] = 0.0f;

        // kk-pairs: one LDS.128 per operand feeds 2 chunks
        #pragma unroll
        for (int P = 0; P < 8; ++P) {
            uint32_t a[2][2][4];   // [mi][chunk]
            #pragma unroll
            for (int mi = 0; mi < 2; ++mi) {
                int rb = wm * 32 + mi * 16;
                uint4 u0 = *(const uint4*)&Asu[(rb + g) * PPAD + P * 16 + 4 * t];
                uint4 u1 = *(const uint4*)&Asu[(rb + g + 8) * PPAD + P * 16 + 4 * t];
                a[mi][0][0] = u0.x; a[mi][0][2] = u0.y;
                a[mi][1][0] = u0.z; a[mi][1][2] = u0.w;
                a[mi][0][1] = u1.x; a[mi][0][3] = u1.y;
                a[mi][1][1] = u1.z; a[mi][1][3] = u1.w;
            }
            #pragma unroll
            for (int nt = 0; nt < 8; ++nt) {
                uint4 bp = *(const uint4*)&Wtu[(wn * 64 + nt * 8 + g) * PPAD + P * 16 + 4 * t];
                mma8(acc[0][nt], a[0][0], bp.x, bp.y);
                mma8(acc[0][nt], a[0][1], bp.z, bp.w);
                mma8(acc[1][nt], a[1][0], bp.x, bp.y);
                mma8(acc[1][nt], a[1][1], bp.z, bp.w);
            }
        }

        __syncthreads();   // all warps done reading Wtu
        if (wi + 1 < nw) { // prefetch next W; copy hides under the epilogue
            int n = tid >> 2, q4 = tid & 3;
            const float4* src = (const float4*)&g_wt[wbase + wi + 1][n][q4 * 32];
            uint32_t* dst = Wtu + n * PPAD + q4 * 32;
            #pragma unroll
            for (int c = 0; c < 8; ++c)
                cpa16(dst + c * 4, src + c);
            asm volatile("cp.async.commit_group;\n");
        }

        // epilogue
        #pragma unroll
        for (int mi = 0; mi < 2; ++mi) {
            int row0 = bm + wm * 32 + mi * 16 + g;
            int row1 = row0 + 8;
            int i0 = row0 / JDIM, j0 = row0 - i0 * JDIM;
            int i1 = row1 / JDIM, j1 = row1 - i1 * JDIM;
            int pj0 = permv(j0), pj1 = permv(j1);
            #pragma unroll
            for (int nt = 0; nt < 8; ++nt) {
                int col = wn * 64 + nt * 8 + 2 * t;
                float v0 = acc[mi][nt][0], v1 = acc[mi][nt][1];
                float v2 = acc[mi][nt][2], v3 = acc[mi][nt][3];
                if (amode == 0) {
                    if (wi <= 1) {          // q/k: cols already slot16 order
                        int r0 = (wi == 1) ? perm8(row0) : row0;
                        int r1 = (wi == 1) ? perm8(row1) : row1;
                        float2 a0 = { __uint_as_float(f2tf(v0)), __uint_as_float(f2tf(v1)) };
                        float2 a1 = { __uint_as_float(f2tf(v2)), __uint_as_float(f2tf(v3)) };
                        *(float2*)(g_qkvg + (size_t)r0 * 512 + wi * 128 + col) = a0;
                        *(float2*)(g_qkvg + (size_t)r1 * 512 + wi * 128 + col) = a1;
                    } else if (wi == 2) {   // v: transposed tf32 into g_vt, permv cols
                        int hh = col >> 5, d0 = col & 31;
                        size_t b0 = ((size_t)(i0 * NH + hh) * HD + d0) * JDIM;
                        size_t b1 = ((size_t)(i1 * NH + hh) * HD + d0) * JDIM;
                        g_vt[b0 + pj0]        = __uint_as_float(f2tf(v0));
                        g_vt[b0 + JDIM + pj0] = __uint_as_float(f2tf(v1));
                        g_vt[b1 + pj1]        = __uint_as_float(f2tf(v2));
                        g_vt[b1 + JDIM + pj1] = __uint_as_float(f2tf(v3));
                    } else {                // g: + bias, fp32 natural
                        float2 bb = *(const float2*)(bias + col);
                        float2 a0 = { v0 + bb.x, v1 + bb.y };
                        float2 a1 = { v2 + bb.x, v3 + bb.y };
                        *(float2*)(g_qkvg + (size_t)row0 * 512 + 384 + col) = a0;
                        *(float2*)(g_qkvg + (size_t)row1 * 512 + 384 + col) = a1;
                    }
                } else {
                    float2 bb = *(const float2*)(bias + col);
                    float2 a0 = { v0 + bb.x, v1 + bb.y };
                    float2 a1 = { v2 + bb.x, v3 + bb.y };
                    *(float2*)(Cext + (size_t)row0 * 128 + col) = a0;
                    *(float2*)(Cext + (size_t)row1 * 128 + col) = a1;
                }
            }
        }
    }
}

// ---------------------------------------------------------------------------
// Kernel D: tf32 mma flash attention (R12, byte-identical). 192 threads,
// 6 warps x 32 q-rows, q-tile 192, 2 blocks/SM. All fragment loads 128-bit.
// ---------------------------------------------------------------------------
constexpr int KS_W = 80;
constexpr int VT_W = 80;
constexpr size_t SMEM_ATTN = (size_t)(2 * 64 * KS_W + 2 * 32 * VT_W + 384) * 4;

__global__ void __launch_bounds__(192, 2) attn_mma() {
    extern __shared__ uint32_t sm[];
    uint32_t* Ks = sm;                    // [2][64][KS_W]
    uint32_t* Vt = sm + 2 * 64 * KS_W;    // [2][32][VT_W]
    float*    mb = (float*)(Vt + 2 * 32 * VT_W);

    const int qt  = blockIdx.x;       // 0..1
    const int h   = blockIdx.y;       // 0..3
    const int i   = blockIdx.z;       // 0..383
    const int tid = threadIdx.x;
    const int w = tid >> 5, lane = tid & 31;
    const int g = lane >> 2, t = lane & 3;
    const int q0 = qt * 192;

    if (tid < 96)
        ((float4*)mb)[tid] = *(const float4*)(g_mb + (size_t)i * JDIM + tid * 4);

    // Q fragments: slot16 storage -> one LDG.128 per chunk-pair per row
    uint32_t qa[2][4][4];
    #pragma unroll
    for (int mi = 0; mi < 2; ++mi) {
        int qr = q0 + w * 32 + mi * 16 + g;
        const float* p0 = g_qkvg + ((size_t)i * JDIM + qr) * 512 + h * HD;
        const float* p1 = p0 + 8 * 512;
        #pragma unroll
        for (int P = 0; P < 2; ++P) {
            uint4 u0 = *(const uint4*)(p0 + P * 16 + 4 * t);
            uint4 u1 = *(const uint4*)(p1 + P * 16 + 4 * t);
            qa[mi][2*P  ][0] = u0.x; qa[mi][2*P  ][2] = u0.y;
            qa[mi][2*P+1][0] = u0.z; qa[mi][2*P+1][2] = u0.w;
            qa[mi][2*P  ][1] = u1.x; qa[mi][2*P  ][3] = u1.y;
            qa[mi][2*P+1][1] = u1.z; qa[mi][2*P+1][3] = u1.w;
        }
    }

    const float* kbase = g_qkvg + ((size_t)i * JDIM) * 512 + 128 + h * HD;
    const float* vbase = g_vt + (size_t)(i * NH + h) * HD * JDIM;

    auto stage = [&](int st, int k0) {
        #pragma unroll
        for (int c = tid; c < 1024; c += 192) {
            if (c < 512) {
                int r = c >> 3, seg = c & 7;
                cpa16(Ks + (st * 64 + r) * KS_W + seg * 4,
                      kbase + (size_t)(k0 + r) * 512 + seg * 4);
            } else {
                int vc = c - 512;
                int d = vc >> 4, seg = vc & 15;
                cpa16(Vt + (st * 32 + d) * VT_W + seg * 4,
                      vbase + (size_t)d * JDIM + k0 + seg * 4);
            }
        }
        asm volatile("cp.async.commit_group;\n");
    };

    stage(0, 0);

    float l[2][2] = { {0.f, 0.f}, {0.f, 0.f} };
    float o[2][4][4];
    #pragma unroll
    for (int mi = 0; mi < 2; ++mi)
        #pragma unroll
        for (int nt = 0; nt < 4; ++nt)
            #pragma unroll
            for (int j = 0; j < 4; ++j) o[mi][nt][j] = 0.0f;

    const float* tb = g_tri + (size_t)h * NPIX;

    for (int kt = 0; kt < 6; ++kt) {
        const int k0 = kt * 64;
        const int st = kt & 1;

        // S init = tri bias (permv layout -> LDG.128 fills two chunks)
        float s[2][8][4];
        #pragma unroll
        for (int mi = 0; mi < 2; ++mi) {
            const float* t0 = tb + (size_t)(q0 + w * 32 + mi * 16 + g) * JDIM + k0;
            const float* t1 = t0 + 8 * JDIM;
            #pragma unroll
            for (int P = 0; P < 4; ++P) {
                float4 a = *(const float4*)(t0 + P * 16 + 4 * t);
                float4 b = *(const float4*)(t1 + P * 16 + 4 * t);
                s[mi][2*P  ][0] = a.x; s[mi][2*P  ][1] = a.y;
                s[mi][2*P+1][0] = a.z; s[mi][2*P+1][1] = a.w;
                s[mi][2*P  ][2] = b.x; s[mi][2*P  ][3] = b.y;
                s[mi][2*P+1][2] = b.z; s[mi][2*P+1][3] = b.w;
            }
        }

        asm volatile("cp.async.wait_group 0;\n");
        __syncthreads();
        if (kt < 5) stage(st ^ 1, k0 + 64);

        // + mask bias (LDS.128 covers two chunks), S += Q K^T
        #pragma unroll
        for (int P = 0; P < 4; ++P) {
            float4 mv = *(const float4*)&mb[k0 + P * 16 + 4 * t];
            #pragma unroll
            for (int mi = 0; mi < 2; ++mi) {
                s[mi][2*P  ][0] += mv.x; s[mi][2*P  ][1] += mv.y;
                s[mi][2*P  ][2] += mv.x; s[mi][2*P  ][3] += mv.y;
                s[mi][2*P+1][0] += mv.z; s[mi][2*P+1][1] += mv.w;
                s[mi][2*P+1][2] += mv.z; s[mi][2*P+1][3] += mv.w;
            }
        }
        #pragma unroll
        for (int nt = 0; nt < 8; ++nt) {
            const uint32_t* krow = Ks + (st * 64 + nt * 8 + g) * KS_W;
            #pragma unroll
            for (int P = 0; P < 2; ++P) {
                uint4 bp = *(const uint4*)(krow + P * 16 + 4 * t);
                mma8(s[0][nt], qa[0][2*P  ], bp.x, bp.y);
                mma8(s[0][nt], qa[0][2*P+1], bp.z, bp.w);
                mma8(s[1][nt], qa[1][2*P  ], bp.x, bp.y);
                mma8(s[1][nt], qa[1][2*P+1], bp.z, bp.w);
            }
        }

        // p = exp2(s); accumulate l (ex2 saturates masked scores to 0)
        #pragma unroll
        for (int mi = 0; mi < 2; ++mi)
            #pragma unroll
            for (int nt = 0; nt < 8; ++nt) {
                s[mi][nt][0] = ex2(s[mi][nt][0]);
                s[mi][nt][1] = ex2(s[mi][nt][1]);
                s[mi][nt][2] = ex2(s[mi][nt][2]);
                s[mi][nt][3] = ex2(s[mi][nt][3]);
                l[mi][0] += s[mi][nt][0] + s[mi][nt][1];
                l[mi][1] += s[mi][nt][2] + s[mi][nt][3];
            }

        // O += P V (one LDS.128 -> 4 MMAs; raw fp32 bits as tf32)
        #pragma unroll
        for (int PP = 0; PP < 4; ++PP) {
            uint32_t pa0a[4], pa0b[4], pa1a[4], pa1b[4];
            int k0c = 2 * PP, k1c = 2 * PP + 1;
            pa0a[0] = __float_as_uint(s[0][k0c][0]); pa0a[1] = __float_as_uint(s[0][k0c][2]);
            pa0a[2] = __float_as_uint(s[0][k0c][1]); pa0a[3] = __float_as_uint(s[0][k0c][3]);
            pa0b[0] = __float_as_uint(s[0][k1c][0]); pa0b[1] = __float_as_uint(s[0][k1c][2]);
            pa0b[2] = __float_as_uint(s[0][k1c][1]); pa0b[3] = __float_as_uint(s[0][k1c][3]);
            pa1a[0] = __float_as_uint(s[1][k0c][0]); pa1a[1] = __float_as_uint(s[1][k0c][2]);
            pa1a[2] = __float_as_uint(s[1][k0c][1]); pa1a[3] = __float_as_uint(s[1][k0c][3]);
            pa1b[0] = __float_as_uint(s[1][k1c][0]); pa1b[1] = __float_as_uint(s[1][k1c][2]);
            pa1b[2] = __float_as_uint(s[1][k1c][1]); pa1b[3] = __float_as_uint(s[1][k1c][3]);
            #pragma unroll
            for (int nt = 0; nt < 4; ++nt) {
                uint4 bp = *(const uint4*)(Vt + (st * 32 + nt * 8 + g) * VT_W + PP * 16 + 4 * t);
                mma8(o[0][nt], pa0a, bp.x, bp.y);
                mma8(o[0][nt], pa0b, bp.z, bp.w);
                mma8(o[1][nt], pa1a, bp.x, bp.y);
                mma8(o[1][nt], pa1b, bp.z, bp.w);
            }
        }
    }

    // epilogue: reduce l, normalize, gate, store natural tf32 bits (coalesced)
    #pragma unroll
    for (int mi = 0; mi < 2; ++mi) {
        float l0 = l[mi][0], l1 = l[mi][1];
        l0 += __shfl_xor_sync(0xffffffffu, l0, 1);
        l0 += __shfl_xor_sync(0xffffffffu, l0, 2);
        l1 += __shfl_xor_sync(0xffffffffu, l1, 1);
        l1 += __shfl_xor_sync(0xffffffffu, l1, 2);
        float inv0 = 1.0f / l0, inv1 = 1.0f / l1;

        int qr = q0 + w * 32 + mi * 16 + g;
        size_t pix0 = (size_t)i * JDIM + qr;
        size_t pix1 = pix0 + 8;
        const float* gt0 = g_qkvg + pix0 * 512 + 384 + h * HD;
        const float* gt1 = g_qkvg + pix1 * 512 + 384 + h * HD;
        float* o0 = g_og + pix0 * CH + h * HD;
        float* o1 = g_og + pix1 * CH + h * HD;
        #pragma unroll
        for (int nt = 0; nt < 4; ++nt) {
            int d = nt * 8 + 2 * t;
            float2 gv0 = *(const float2*)(gt0 + d);
            float2 gv1 = *(const float2*)(gt1 + d);
            float2 r0, r1;
            r0.x = __uint_as_float(f2tf(o[mi][nt][0] * inv0 * (1.0f / (1.0f + __expf(-gv0.x)))));
            r0.y = __uint_as_float(f2tf(o[mi][nt][1] * inv0 * (1.0f / (1.0f + __expf(-gv0.y)))));
            r1.x = __uint_as_float(f2tf(o[mi][nt][2] * inv1 * (1.0f / (1.0f + __expf(-gv1.x)))));
            r1.y = __uint_as_float(f2tf(o[mi][nt][3] * inv1 * (1.0f / (1.0f + __expf(-gv1.y)))));
            *(float2*)(o0 + d) = r0;
            *(float2*)(o1 + d) = r1;
        }
    }
}

// ---------------------------------------------------------------------------
// Launch.  Inputs: x, mask, ln_w, ln_b, w_tri, wq, wk, wv, wg, bg, wo, bo
// ---------------------------------------------------------------------------
extern "C" void kernel_launch(void* const* d_in, const int* in_sizes, int n_in,
                              void* d_out, int out_size) {
    const float* x     = (const float*)d_in[0];
    const float* mask  = (const float*)d_in[1];
    const float* ln_w  = (const float*)d_in[2];
    const float* ln_b  = (const float*)d_in[3];
    const float* w_tri = (const float*)d_in[4];
    const float* bg    = (const float*)d_in[9];
    const float* bo    = (const float*)d_in[11];
    float* out = (float*)d_out;

    static bool attr_done = false;
    if (!attr_done) {
        cudaFuncSetAttribute(proj_kernel,
                             cudaFuncAttributeMaxDynamicSharedMemorySize,
                             (int)SMEM_PROJ);
        cudaFuncSetAttribute(attn_mma,
                             cudaFuncAttributeMaxDynamicSharedMemorySize,
                             (int)SMEM_ATTN);
        attr_done = true;
    }

    // merged weight + mask prep (blocks 0-4 weights, 5+ mask rows)
    prep_kernel<<<5 + (NPIX + 255) / 256, 256>>>(
        (const float*)d_in[5], (const float*)d_in[6], (const float*)d_in[7],
        (const float*)d_in[8], (const float*)d_in[10], mask);

    // fused LN + tri + q,k,v,g projections
    proj_kernel<<<NPIX / 256, 512, SMEM_PROJ>>>(0, 4, bg,
                                                x, ln_w, ln_b, w_tri,
                                                nullptr, 0);

    // attention (tri + mask bias, gating fused)
    attn_mma<<<dim3(2, NH, IDIM), 192, SMEM_ATTN>>>();

    // output projection
    proj_kernel<<<NPIX / 256, 512, SMEM_PROJ>>>(4, 1, bo,
                                                nullptr, nullptr, nullptr, nullptr,
                                                out, 1);
}

// round 16
// speedup vs baseline: 1.1033x; 1.0014x over previous
#include <cuda_runtime.h>
#include <cstdint>

constexpr int IDIM = 384;
constexpr int JDIM = 384;
constexpr int NPIX = IDIM * JDIM;      // 147456
constexpr int CH   = 128;
constexpr int NH   = 4;
constexpr int HD   = 32;
constexpr float LN_EPS = 1e-5f;
constexpr float QSCALE = 0.17677669529663687f;  // 1/sqrt(32)
constexpr float LOG2E  = 1.4426950408889634f;

// Static device scratch
__device__ float g_qkvg[(size_t)NPIX * 512];   // q|k|-|g (q,k tf32 slot16-interleaved, k rows perm8'd, q pre-scaled; g = sigmoid, fp32)
__device__ float g_vt[(size_t)IDIM * NH * HD * JDIM];  // V^T: [i][h][d][permv(j)], tf32 bits
__device__ float g_tri[(size_t)NH * NPIX];     // tri bias * log2e, k-index permv'd
__device__ float g_mb[(size_t)NPIX];           // 1e9*log2e*(mask-1), k-index permv'd
__device__ float g_og[(size_t)NPIX * CH];      // gated attn out, natural, raw fp32
__device__ uint32_t g_wt[5][128][128];         // transposed tf32 weights, k slot16'd; wq/wk N-cols slot16'd

// ---------------------------------------------------------------------------
__device__ __forceinline__ uint32_t f2tf(float f) {
    uint32_t u;
    asm("cvt.rna.tf32.f32 %0, %1;" : "=r"(u) : "f"(f));
    return u;
}
__device__ __forceinline__ float ex2(float x) {
    float y;
    asm("ex2.approx.f32 %0, %1;" : "=f"(y) : "f"(x));
    return y;
}
__device__ __forceinline__ void mma8(float* d, const uint32_t* a,
                                     uint32_t b0, uint32_t b1) {
    asm volatile(
        "mma.sync.aligned.m16n8k8.row.col.f32.tf32.tf32.f32 "
        "{%0,%1,%2,%3}, {%4,%5,%6,%7}, {%8,%9}, {%0,%1,%2,%3};\n"
        : "+f"(d[0]), "+f"(d[1]), "+f"(d[2]), "+f"(d[3])
        : "r"(a[0]), "r"(a[1]), "r"(a[2]), "r"(a[3]), "r"(b0), "r"(b1));
}
__device__ __forceinline__ void cpa16(void* dst, const void* src) {
    unsigned d = (unsigned)__cvta_generic_to_shared(dst);
    asm volatile("cp.async.cg.shared.global [%0], [%1], 16;\n"
                 :: "r"(d), "l"(src));
}
// pair-interleave within groups of 8 (== mma fragment slot map)
__device__ __forceinline__ int perm8(int x) {
    return (x & ~7) | (((x & 3) << 1) | ((x >> 2) & 1));
}
// dim d -> storage pos: chunk-PAIR fragment words contiguous (16B = 4 frag words)
__device__ __forceinline__ int slot16(int x) {
    int w = x & 15, c = w >> 3, v = w & 7;
    return (x & ~15) | ((v & 3) << 2) | (c << 1) | (v >> 2);
}
// key j -> storage col: sigma within 8, then chunk-pair interleave
__device__ __forceinline__ int permv(int j) {
    int p8 = perm8(j) & 7;
    int c  = (j >> 3) & 1;
    return (j & ~15) | ((p8 >> 1) << 2) | (c << 1) | (p8 & 1);
}

// ---------------------------------------------------------------------------
// Kernel A: merged one-shot prep. Blocks 0-4: weight transpose + tf32 +
// slot16 perms (+ wq scale). Blocks 5+: permv'd mask-bias rows.
// ---------------------------------------------------------------------------
__global__ void prep_kernel(const float* __restrict__ wq,
                            const float* __restrict__ wk,
                            const float* __restrict__ wv,
                            const float* __restrict__ wg,
                            const float* __restrict__ wo,
                            const float* __restrict__ mask) {
    if (blockIdx.x < 5) {
        const float* Ws[5] = { wq, wk, wv, wg, wo };
        int wi = blockIdx.x;
        if (threadIdx.x >= 128) return;
        int k = threadIdx.x;
        float scale = (wi == 0) ? (QSCALE * LOG2E) : 1.0f;
        const float4* src = (const float4*)(Ws[wi] + (size_t)k * 128);
        int pk = slot16(k);
        bool nperm = (wi <= 1);
        #pragma unroll
        for (int c = 0; c < 32; ++c) {
            float4 v = src[c];
            float vv[4] = { v.x, v.y, v.z, v.w };
            #pragma unroll
            for (int e = 0; e < 4; ++e) {
                int n = c * 4 + e;
                int np = nperm ? slot16(n) : n;
                g_wt[wi][np][pk] = f2tf(vv[e] * scale);
            }
        }
    } else {
        int idx = (blockIdx.x - 5) * 256 + threadIdx.x;
        if (idx >= NPIX) return;
        int i = idx / JDIM;
        int j = idx - i * JDIM;
        g_mb[(size_t)i * JDIM + permv(j)] = (1e9f * LOG2E) * (mask[idx] - 1.0f);
    }
}

// ---------------------------------------------------------------------------
// Kernel C: fused {LayerNorm + tri-proj} + tf32 mma projections.
// Stage-A packs 16 channels in registers, rotated STS.128 (conflict-free).
// Mainloop: LDS.128 fragment loads feeding 4 MMAs. PPAD 144.
// g output stores sigmoid(g) directly (consumed only as gate).
// ---------------------------------------------------------------------------
constexpr int PPAD = 144;
constexpr size_t SMEM_PROJ = (size_t)(256 * PPAD + 128 * PPAD + 768) * 4;

__global__ void __launch_bounds__(512) proj_kernel(
        int wbase, int nw, const float* __restrict__ bias,
        const float* __restrict__ X,
        const float* __restrict__ ln_w, const float* __restrict__ ln_b,
        const float* __restrict__ w_tri,
        float* __restrict__ Cext, int amode) {
    extern __shared__ uint32_t smu[];
    uint32_t* Asu = smu;                    // [256][PPAD]
    uint32_t* Wtu = smu + 256 * PPAD;       // [128][PPAD]
    float* lnw  = (float*)(Wtu + 128 * PPAD);
    float* lnb  = lnw + 128;
    float* wtri = lnb + 128;

    const int tid = threadIdx.x;
    const int bm  = blockIdx.x * 256;

    // prefetch W0 while A is being staged
    {
        int n = tid >> 2, q4 = tid & 3;
        const float4* src = (const float4*)&g_wt[wbase][n][q4 * 32];
        uint32_t* dst = Wtu + n * PPAD + q4 * 32;
        #pragma unroll
        for (int c = 0; c < 8; ++c)
            cpa16(dst + c * 4, src + c);
        asm volatile("cp.async.commit_group;\n");
    }

    if (amode == 0) {
        if (tid < 32)        ((float4*)lnw)[tid]       = ((const float4*)ln_w)[tid];
        else if (tid < 64)   ((float4*)lnb)[tid - 32]  = ((const float4*)ln_b)[tid - 32];
        else if (tid < 192)  ((float4*)wtri)[tid - 64] = ((const float4*)w_tri)[tid - 64];
    }
    __syncthreads();

    // ---- stage A (slot16 k-layout; packed STS.128 with per-row rotation) ----
    {
        int r = tid >> 1, half = tid & 1;
        int gw = bm + r;
        uint32_t* arow = Asu + r * PPAD + half * 64;
        const int rot = (r >> 1) & 3;

        if (amode == 0) {
            const float4* xr = (const float4*)(X + (size_t)gw * 128 + half * 64);
            float s = 0.f, ss = 0.f;
            #pragma unroll
            for (int c = 0; c < 16; ++c) {
                float4 v = xr[c];
                s  += v.x + v.y + v.z + v.w;
                ss += v.x * v.x + v.y * v.y + v.z * v.z + v.w * v.w;
            }
            s  += __shfl_xor_sync(0xffffffffu, s, 1);
            ss += __shfl_xor_sync(0xffffffffu, ss, 1);
            float mu = s * (1.0f / 128.0f);
            float rs = rsqrtf(fmaxf(ss * (1.0f / 128.0f) - mu * mu, 0.f) + LN_EPS);

            float th0 = 0.f, th1 = 0.f, th2 = 0.f, th3 = 0.f;
            #pragma unroll
            for (int grp = 0; grp < 4; ++grp) {
                float xng[16];
                #pragma unroll
                for (int c4 = 0; c4 < 4; ++c4) {
                    float4 v = xr[grp * 4 + c4];
                    float vs[4] = { v.x, v.y, v.z, v.w };
                    #pragma unroll
                    for (int e = 0; e < 4; ++e) {
                        int ch = half * 64 + grp * 16 + c4 * 4 + e;
                        float xn = (vs[e] - mu) * rs * lnw[ch] + lnb[ch];
                        float4 wt = ((const float4*)wtri)[ch];
                        th0 += xn * wt.x; th1 += xn * wt.y;
                        th2 += xn * wt.z; th3 += xn * wt.w;
                        xng[c4 * 4 + e] = xn;
                    }
                }
                #pragma unroll
                for (int idx = 0; idx < 4; ++idx) {
                    int tp = (idx + rot) & 3;
                    uint4 u = { f2tf(xng[tp]),     f2tf(xng[tp + 4]),
                                f2tf(xng[tp + 8]), f2tf(xng[tp + 12]) };
                    *(uint4*)(arow + grp * 16 + 4 * tp) = u;
                }
            }
            th0 += __shfl_xor_sync(0xffffffffu, th0, 1);
            th1 += __shfl_xor_sync(0xffffffffu, th1, 1);
            th2 += __shfl_xor_sync(0xffffffffu, th2, 1);
            th3 += __shfl_xor_sync(0xffffffffu, th3, 1);
            if (half == 0) {
                size_t dst = (size_t)permv(gw);
                g_tri[0 * (size_t)NPIX + dst] = th0 * LOG2E;
                g_tri[1 * (size_t)NPIX + dst] = th1 * LOG2E;
                g_tri[2 * (size_t)NPIX + dst] = th2 * LOG2E;
                g_tri[3 * (size_t)NPIX + dst] = th3 * LOG2E;
            }
        } else {
            const float4* xr = (const float4*)(g_og + (size_t)gw * 128 + half * 64);
            #pragma unroll
            for (int grp = 0; grp < 4; ++grp) {
                uint32_t xng[16];
                #pragma unroll
                for (int c4 = 0; c4 < 4; ++c4) {
                    float4 v = xr[grp * 4 + c4];
                    xng[c4 * 4 + 0] = __float_as_uint(v.x);
                    xng[c4 * 4 + 1] = __float_as_uint(v.y);
                    xng[c4 * 4 + 2] = __float_as_uint(v.z);
                    xng[c4 * 4 + 3] = __float_as_uint(v.w);
                }
                #pragma unroll
                for (int idx = 0; idx < 4; ++idx) {
                    int tp = (idx + rot) & 3;
                    uint4 u = { xng[tp], xng[tp + 4], xng[tp + 8], xng[tp + 12] };
                    *(uint4*)(arow + grp * 16 + 4 * tp) = u;
                }
            }
        }
    }

    const int w = tid >> 5, lane = tid & 31;
    const int g = lane >> 2, t = lane & 3;
    const int wm = w >> 1, wn = w & 1;

    for (int wi = 0; wi < nw; ++wi) {
        asm volatile("cp.async.wait_group 0;\n");
        __syncthreads();

        float acc[2][8][4];
        #pragma unroll
        for (int mi = 0; mi < 2; ++mi)
            #pragma unroll
            for (int nt = 0; nt < 8; ++nt)
                #pragma unroll
                for (int j = 0; j < 4; ++j) acc[mi][nt][j] = 0.0f;

        // kk-pairs: one LDS.128 per operand feeds 2 chunks
        #pragma unroll
        for (int P = 0; P < 8; ++P) {
            uint32_t a[2][2][4];   // [mi][chunk]
            #pragma unroll
            for (int mi = 0; mi < 2; ++mi) {
                int rb = wm * 32 + mi * 16;
                uint4 u0 = *(const uint4*)&Asu[(rb + g) * PPAD + P * 16 + 4 * t];
                uint4 u1 = *(const uint4*)&Asu[(rb + g + 8) * PPAD + P * 16 + 4 * t];
                a[mi][0][0] = u0.x; a[mi][0][2] = u0.y;
                a[mi][1][0] = u0.z; a[mi][1][2] = u0.w;
                a[mi][0][1] = u1.x; a[mi][0][3] = u1.y;
                a[mi][1][1] = u1.z; a[mi][1][3] = u1.w;
            }
            #pragma unroll
            for (int nt = 0; nt < 8; ++nt) {
                uint4 bp = *(const uint4*)&Wtu[(wn * 64 + nt * 8 + g) * PPAD + P * 16 + 4 * t];
                mma8(acc[0][nt], a[0][0], bp.x, bp.y);
                mma8(acc[0][nt], a[0][1], bp.z, bp.w);
                mma8(acc[1][nt], a[1][0], bp.x, bp.y);
                mma8(acc[1][nt], a[1][1], bp.z, bp.w);
            }
        }

        __syncthreads();   // all warps done reading Wtu
        if (wi + 1 < nw) { // prefetch next W; copy hides under the epilogue
            int n = tid >> 2, q4 = tid & 3;
            const float4* src = (const float4*)&g_wt[wbase + wi + 1][n][q4 * 32];
            uint32_t* dst = Wtu + n * PPAD + q4 * 32;
            #pragma unroll
            for (int c = 0; c < 8; ++c)
                cpa16(dst + c * 4, src + c);
            asm volatile("cp.async.commit_group;\n");
        }

        // epilogue
        #pragma unroll
        for (int mi = 0; mi < 2; ++mi) {
            int row0 = bm + wm * 32 + mi * 16 + g;
            int row1 = row0 + 8;
            int i0 = row0 / JDIM, j0 = row0 - i0 * JDIM;
            int i1 = row1 / JDIM, j1 = row1 - i1 * JDIM;
            int pj0 = permv(j0), pj1 = permv(j1);
            #pragma unroll
            for (int nt = 0; nt < 8; ++nt) {
                int col = wn * 64 + nt * 8 + 2 * t;
                float v0 = acc[mi][nt][0], v1 = acc[mi][nt][1];
                float v2 = acc[mi][nt][2], v3 = acc[mi][nt][3];
                if (amode == 0) {
                    if (wi <= 1) {          // q/k: cols already slot16 order
                        int r0 = (wi == 1) ? perm8(row0) : row0;
                        int r1 = (wi == 1) ? perm8(row1) : row1;
                        float2 a0 = { __uint_as_float(f2tf(v0)), __uint_as_float(f2tf(v1)) };
                        float2 a1 = { __uint_as_float(f2tf(v2)), __uint_as_float(f2tf(v3)) };
                        *(float2*)(g_qkvg + (size_t)r0 * 512 + wi * 128 + col) = a0;
                        *(float2*)(g_qkvg + (size_t)r1 * 512 + wi * 128 + col) = a1;
                    } else if (wi == 2) {   // v: transposed tf32 into g_vt, permv cols
                        int hh = col >> 5, d0 = col & 31;
                        size_t b0 = ((size_t)(i0 * NH + hh) * HD + d0) * JDIM;
                        size_t b1 = ((size_t)(i1 * NH + hh) * HD + d0) * JDIM;
                        g_vt[b0 + pj0]        = __uint_as_float(f2tf(v0));
                        g_vt[b0 + JDIM + pj0] = __uint_as_float(f2tf(v1));
                        g_vt[b1 + pj1]        = __uint_as_float(f2tf(v2));
                        g_vt[b1 + pj1 + JDIM] = __uint_as_float(f2tf(v3));
                    } else {                // g: + bias, SIGMOID, fp32 natural
                        float2 bb = *(const float2*)(bias + col);
                        float2 a0, a1;
                        a0.x = 1.0f / (1.0f + __expf(-(v0 + bb.x)));
                        a0.y = 1.0f / (1.0f + __expf(-(v1 + bb.y)));
                        a1.x = 1.0f / (1.0f + __expf(-(v2 + bb.x)));
                        a1.y = 1.0f / (1.0f + __expf(-(v3 + bb.y)));
                        *(float2*)(g_qkvg + (size_t)row0 * 512 + 384 + col) = a0;
                        *(float2*)(g_qkvg + (size_t)row1 * 512 + 384 + col) = a1;
                    }
                } else {
                    float2 bb = *(const float2*)(bias + col);
                    float2 a0 = { v0 + bb.x, v1 + bb.y };
                    float2 a1 = { v2 + bb.x, v3 + bb.y };
                    *(float2*)(Cext + (size_t)row0 * 128 + col) = a0;
                    *(float2*)(Cext + (size_t)row1 * 128 + col) = a1;
                }
            }
        }
    }
}

// ---------------------------------------------------------------------------
// Kernel D: tf32 mma flash attention (R15 structure). 192 threads, 6 warps
// x 32 q-rows, q-tile 192, 2 blocks/SM. All fragment loads 128-bit.
// Epilogue: gate is precomputed sigmoid; og stored as raw fp32 (no f2tf).
// ---------------------------------------------------------------------------
constexpr int KS_W = 80;
constexpr int VT_W = 80;
constexpr size_t SMEM_ATTN = (size_t)(2 * 64 * KS_W + 2 * 32 * VT_W + 384) * 4;

__global__ void __launch_bounds__(192, 2) attn_mma() {
    extern __shared__ uint32_t sm[];
    uint32_t* Ks = sm;                    // [2][64][KS_W]
    uint32_t* Vt = sm + 2 * 64 * KS_W;    // [2][32][VT_W]
    float*    mb = (float*)(Vt + 2 * 32 * VT_W);

    const int qt  = blockIdx.x;       // 0..1
    const int h   = blockIdx.y;       // 0..3
    const int i   = blockIdx.z;       // 0..383
    const int tid = threadIdx.x;
    const int w = tid >> 5, lane = tid & 31;
    const int g = lane >> 2, t = lane & 3;
    const int q0 = qt * 192;

    if (tid < 96)
        ((float4*)mb)[tid] = *(const float4*)(g_mb + (size_t)i * JDIM + tid * 4);

    // Q fragments: slot16 storage -> one LDG.128 per chunk-pair per row
    uint32_t qa[2][4][4];
    #pragma unroll
    for (int mi = 0; mi < 2; ++mi) {
        int qr = q0 + w * 32 + mi * 16 + g;
        const float* p0 = g_qkvg + ((size_t)i * JDIM + qr) * 512 + h * HD;
        const float* p1 = p0 + 8 * 512;
        #pragma unroll
        for (int P = 0; P < 2; ++P) {
            uint4 u0 = *(const uint4*)(p0 + P * 16 + 4 * t);
            uint4 u1 = *(const uint4*)(p1 + P * 16 + 4 * t);
            qa[mi][2*P  ][0] = u0.x; qa[mi][2*P  ][2] = u0.y;
            qa[mi][2*P+1][0] = u0.z; qa[mi][2*P+1][2] = u0.w;
            qa[mi][2*P  ][1] = u1.x; qa[mi][2*P  ][3] = u1.y;
            qa[mi][2*P+1][1] = u1.z; qa[mi][2*P+1][3] = u1.w;
        }
    }

    const float* kbase = g_qkvg + ((size_t)i * JDIM) * 512 + 128 + h * HD;
    const float* vbase = g_vt + (size_t)(i * NH + h) * HD * JDIM;

    auto stage = [&](int st, int k0) {
        #pragma unroll
        for (int c = tid; c < 1024; c += 192) {
            if (c < 512) {
                int r = c >> 3, seg = c & 7;
                cpa16(Ks + (st * 64 + r) * KS_W + seg * 4,
                      kbase + (size_t)(k0 + r) * 512 + seg * 4);
            } else {
                int vc = c - 512;
                int d = vc >> 4, seg = vc & 15;
                cpa16(Vt + (st * 32 + d) * VT_W + seg * 4,
                      vbase + (size_t)d * JDIM + k0 + seg * 4);
            }
        }
        asm volatile("cp.async.commit_group;\n");
    };

    stage(0, 0);

    float l[2][2] = { {0.f, 0.f}, {0.f, 0.f} };
    float o[2][4][4];
    #pragma unroll
    for (int mi = 0; mi < 2; ++mi)
        #pragma unroll
        for (int nt = 0; nt < 4; ++nt)
            #pragma unroll
            for (int j = 0; j < 4; ++j) o[mi][nt][j] = 0.0f;

    const float* tb = g_tri + (size_t)h * NPIX;

    for (int kt = 0; kt < 6; ++kt) {
        const int k0 = kt * 64;
        const int st = kt & 1;

        // S init = tri bias (permv layout -> LDG.128 fills two chunks)
        float s[2][8][4];
        #pragma unroll
        for (int mi = 0; mi < 2; ++mi) {
            const float* t0 = tb + (size_t)(q0 + w * 32 + mi * 16 + g) * JDIM + k0;
            const float* t1 = t0 + 8 * JDIM;
            #pragma unroll
            for (int P = 0; P < 4; ++P) {
                float4 a = *(const float4*)(t0 + P * 16 + 4 * t);
                float4 b = *(const float4*)(t1 + P * 16 + 4 * t);
                s[mi][2*P  ][0] = a.x; s[mi][2*P  ][1] = a.y;
                s[mi][2*P+1][0] = a.z; s[mi][2*P+1][1] = a.w;
                s[mi][2*P  ][2] = b.x; s[mi][2*P  ][3] = b.y;
                s[mi][2*P+1][2] = b.z; s[mi][2*P+1][3] = b.w;
            }
        }

        asm volatile("cp.async.wait_group 0;\n");
        __syncthreads();
        if (kt < 5) stage(st ^ 1, k0 + 64);

        // + mask bias (LDS.128 covers two chunks), S += Q K^T
        #pragma unroll
        for (int P = 0; P < 4; ++P) {
            float4 mv = *(const float4*)&mb[k0 + P * 16 + 4 * t];
            #pragma unroll
            for (int mi = 0; mi < 2; ++mi) {
                s[mi][2*P  ][0] += mv.x; s[mi][2*P  ][1] += mv.y;
                s[mi][2*P  ][2] += mv.x; s[mi][2*P  ][3] += mv.y;
                s[mi][2*P+1][0] += mv.z; s[mi][2*P+1][1] += mv.w;
                s[mi][2*P+1][2] += mv.z; s[mi][2*P+1][3] += mv.w;
            }
        }
        #pragma unroll
        for (int nt = 0; nt < 8; ++nt) {
            const uint32_t* krow = Ks + (st * 64 + nt * 8 + g) * KS_W;
            #pragma unroll
            for (int P = 0; P < 2; ++P) {
                uint4 bp = *(const uint4*)(krow + P * 16 + 4 * t);
                mma8(s[0][nt], qa[0][2*P  ], bp.x, bp.y);
                mma8(s[0][nt], qa[0][2*P+1], bp.z, bp.w);
                mma8(s[1][nt], qa[1][2*P  ], bp.x, bp.y);
                mma8(s[1][nt], qa[1][2*P+1], bp.z, bp.w);
            }
        }

        // p = exp2(s); accumulate l (ex2 saturates masked scores to 0)
        #pragma unroll
        for (int mi = 0; mi < 2; ++mi)
            #pragma unroll
            for (int nt = 0; nt < 8; ++nt) {
                s[mi][nt][0] = ex2(s[mi][nt][0]);
                s[mi][nt][1] = ex2(s[mi][nt][1]);
                s[mi][nt][2] = ex2(s[mi][nt][2]);
                s[mi][nt][3] = ex2(s[mi][nt][3]);
                l[mi][0] += s[mi][nt][0] + s[mi][nt][1];
                l[mi][1] += s[mi][nt][2] + s[mi][nt][3];
            }

        // O += P V (one LDS.128 -> 4 MMAs; raw fp32 bits as tf32)
        #pragma unroll
        for (int PP = 0; PP < 4; ++PP) {
            uint32_t pa0a[4], pa0b[4], pa1a[4], pa1b[4];
            int k0c = 2 * PP, k1c = 2 * PP + 1;
            pa0a[0] = __float_as_uint(s[0][k0c][0]); pa0a[1] = __float_as_uint(s[0][k0c][2]);
            pa0a[2] = __float_as_uint(s[0][k0c][1]); pa0a[3] = __float_as_uint(s[0][k0c][3]);
            pa0b[0] = __float_as_uint(s[0][k1c][0]); pa0b[1] = __float_as_uint(s[0][k1c][2]);
            pa0b[2] = __float_as_uint(s[0][k1c][1]); pa0b[3] = __float_as_uint(s[0][k1c][3]);
            pa1a[0] = __float_as_uint(s[1][k0c][0]); pa1a[1] = __float_as_uint(s[1][k0c][2]);
            pa1a[2] = __float_as_uint(s[1][k0c][1]); pa1a[3] = __float_as_uint(s[1][k0c][3]);
            pa1b[0] = __float_as_uint(s[1][k1c][0]); pa1b[1] = __float_as_uint(s[1][k1c][2]);
            pa1b[2] = __float_as_uint(s[1][k1c][1]); pa1b[3] = __float_as_uint(s[1][k1c][3]);
            #pragma unroll
            for (int nt = 0; nt < 4; ++nt) {
                uint4 bp = *(const uint4*)(Vt + (st * 32 + nt * 8 + g) * VT_W + PP * 16 + 4 * t);
                mma8(o[0][nt], pa0a, bp.x, bp.y);
                mma8(o[0][nt], pa0b, bp.z, bp.w);
                mma8(o[1][nt], pa1a, bp.x, bp.y);
                mma8(o[1][nt], pa1b, bp.z, bp.w);
            }
        }
    }

    // epilogue: reduce l, normalize, gate (precomputed sigmoid), store fp32
    #pragma unroll
    for (int mi = 0; mi < 2; ++mi) {
        float l0 = l[mi][0], l1 = l[mi][1];
        l0 += __shfl_xor_sync(0xffffffffu, l0, 1);
        l0 += __shfl_xor_sync(0xffffffffu, l0, 2);
        l1 += __shfl_xor_sync(0xffffffffu, l1, 1);
        l1 += __shfl_xor_sync(0xffffffffu, l1, 2);
        float inv0 = 1.0f / l0, inv1 = 1.0f / l1;

        int qr = q0 + w * 32 + mi * 16 + g;
        size_t pix0 = (size_t)i * JDIM + qr;
        size_t pix1 = pix0 + 8;
        const float* gt0 = g_qkvg + pix0 * 512 + 384 + h * HD;
        const float* gt1 = g_qkvg + pix1 * 512 + 384 + h * HD;
        float* o0 = g_og + pix0 * CH + h * HD;
        float* o1 = g_og + pix1 * CH + h * HD;
        #pragma unroll
        for (int nt = 0; nt < 4; ++nt) {
            int d = nt * 8 + 2 * t;
            float2 gv0 = *(const float2*)(gt0 + d);
            float2 gv1 = *(const float2*)(gt1 + d);
            float2 r0, r1;
            r0.x = o[mi][nt][0] * inv0 * gv0.x;
            r0.y = o[mi][nt][1] * inv0 * gv0.y;
            r1.x = o[mi][nt][2] * inv1 * gv1.x;
            r1.y = o[mi][nt][3] * inv1 * gv1.y;
            *(float2*)(o0 + d) = r0;
            *(float2*)(o1 + d) = r1;
        }
    }
}

// ---------------------------------------------------------------------------
// Launch.  Inputs: x, mask, ln_w, ln_b, w_tri, wq, wk, wv, wg, bg, wo, bo
// ---------------------------------------------------------------------------
extern "C" void kernel_launch(void* const* d_in, const int* in_sizes, int n_in,
                              void* d_out, int out_size) {
    const float* x     = (const float*)d_in[0];
    const float* mask  = (const float*)d_in[1];
    const float* ln_w  = (const float*)d_in[2];
    const float* ln_b  = (const float*)d_in[3];
    const float* w_tri = (const float*)d_in[4];
    const float* bg    = (const float*)d_in[9];
    const float* bo    = (const float*)d_in[11];
    float* out = (float*)d_out;

    static bool attr_done = false;
    if (!attr_done) {
        cudaFuncSetAttribute(proj_kernel,
                             cudaFuncAttributeMaxDynamicSharedMemorySize,
                             (int)SMEM_PROJ);
        cudaFuncSetAttribute(attn_mma,
                             cudaFuncAttributeMaxDynamicSharedMemorySize,
                             (int)SMEM_ATTN);
        attr_done = true;
    }

    // merged weight + mask prep (blocks 0-4 weights, 5+ mask rows)
    prep_kernel<<<5 + (NPIX + 255) / 256, 256>>>(
        (const float*)d_in[5], (const float*)d_in[6], (const float*)d_in[7],
        (const float*)d_in[8], (const float*)d_in[10], mask);

    // fused LN + tri + q,k,v,g projections (g stored as sigmoid)
    proj_kernel<<<NPIX / 256, 512, SMEM_PROJ>>>(0, 4, bg,
                                                x, ln_w, ln_b, w_tri,
                                                nullptr, 0);

    // attention (tri + mask bias, gating fused)
    attn_mma<<<dim3(2, NH, IDIM), 192, SMEM_ATTN>>>();

    // output projection
    proj_kernel<<<NPIX / 256, 512, SMEM_PROJ>>>(4, 1, bo,
                                                nullptr, nullptr, nullptr, nullptr,
                                                out, 1);
}